// round 3
// baseline (speedup 1.0000x reference)
#include <cuda_runtime.h>
#include <math.h>
#include <cfloat>

// Problem constants
// x: (16, 512, 512)  label_reps: (4096, 32, 300)  conv_w: (512, 300, 4)
// conv_b: (512)  lin_w: (512, 512)  lin_b: (512)  label_length: (4096) unused
// out: (16, 4096, 512) float32

// ---------------- scratch (static device memory; no allocation) ----------------
// G: conv GEMM output (131072 x 2048) = 1.07 GB, later reused for attention S (16*4096*512)
__device__ float g_G[(size_t)131072 * 2048];
__device__ float g_Wt[300 * 2048];        // Wt[e][f*4+k] = conv_w[f][e][k]
__device__ float g_linT[512 * 512];       // linT[c][f] = lin_w[f][c]
__device__ float g_xT[16 * 512 * 512];    // xT[b][f][l] = x[b][l][f]
__device__ float g_lr0[4096 * 512];       // conv+relu+maxpool output
__device__ float g_lr[4096 * 512];        // after linear

// ---------------- prep: weight transposes ----------------
__global__ void k_prep_w(const float* __restrict__ conv_w, const float* __restrict__ lin_w)
{
    int i = blockIdx.x * 256 + threadIdx.x;
    if (i < 614400) {
        int e = i / 2048;
        int r = i - e * 2048;
        int f = r >> 2;
        int k = r & 3;
        g_Wt[i] = conv_w[f * 1200 + e * 4 + k];
    }
    if (i < 262144) {
        int c = i >> 9;
        int f = i & 511;
        g_linT[i] = lin_w[f * 512 + c];
    }
}

// ---------------- prep: transpose x to (b, f, l) ----------------
__global__ void k_prep_x(const float* __restrict__ x)
{
    int i = blockIdx.x * 256 + threadIdx.x;   // grid covers 16*512*512
    int b = i >> 18;
    int r = i & 262143;
    int f = r >> 9;
    int l = r & 511;
    g_xT[i] = x[b * 262144 + l * 512 + f];
}

// ---------------- classic 128x128x8 fp32 GEMM, 256 thr, 8x8 per thread ----------------
// C = A(MxK, row-major) * B(KxN, row-major) [+ bias broadcast over rows]
// Requires M % 128 == 0, N % 128 == 0 (true for all call sites). K arbitrary.
// blockIdx.z batches with element strides sA/sB/sC.
__global__ __launch_bounds__(256, 2)
void sgemm128(const float* __restrict__ Abase, const float* __restrict__ Bbase,
              float* __restrict__ Cbase, const float* __restrict__ bias,
              int M, int N, int K, long sA, long sB, long sC)
{
    const float* A = Abase + (long)blockIdx.z * sA;
    const float* Bp = Bbase + (long)blockIdx.z * sB;
    float*       C = Cbase + (long)blockIdx.z * sC;

    __shared__ float As[8][128];   // A tile, stored transposed: As[k][m]
    __shared__ float Bs[8][128];   // Bs[k][n]

    const int tid = threadIdx.x;
    const long brow0 = (long)blockIdx.y * 128;
    const int  bcol0 = blockIdx.x * 128;

    // A-tile load map: 128 rows x 8 cols, 4 scalars per thread (K may be unaligned)
    const int la_r = tid >> 1;
    const int la_c = (tid & 1) << 2;
    // B-tile load map: 8 rows x 128 cols, one float4 per thread
    const int lb_r = tid >> 5;
    const int lb_c = (tid & 31) << 2;

    // compute map: 16x16 threads, each 8x8
    const int tr = (tid >> 4) << 3;
    const int tc = (tid & 15) << 3;

    float acc[8][8];
    #pragma unroll
    for (int i = 0; i < 8; i++)
        #pragma unroll
        for (int j = 0; j < 8; j++)
            acc[i][j] = 0.f;

    const float* Arow = A + (brow0 + la_r) * (long)K;

    for (int k0 = 0; k0 < K; k0 += 8) {
        #pragma unroll
        for (int j = 0; j < 4; j++) {
            int kk = k0 + la_c + j;
            As[la_c + j][la_r] = (kk < K) ? Arow[kk] : 0.f;
        }
        {
            int kb = k0 + lb_r;
            float4 bv = make_float4(0.f, 0.f, 0.f, 0.f);
            if (kb < K)
                bv = *reinterpret_cast<const float4*>(Bp + (long)kb * N + bcol0 + lb_c);
            *reinterpret_cast<float4*>(&Bs[lb_r][lb_c]) = bv;
        }
        __syncthreads();

        #pragma unroll
        for (int kk = 0; kk < 8; kk++) {
            float a[8], b[8];
            *reinterpret_cast<float4*>(&a[0]) = *reinterpret_cast<const float4*>(&As[kk][tr]);
            *reinterpret_cast<float4*>(&a[4]) = *reinterpret_cast<const float4*>(&As[kk][tr + 4]);
            *reinterpret_cast<float4*>(&b[0]) = *reinterpret_cast<const float4*>(&Bs[kk][tc]);
            *reinterpret_cast<float4*>(&b[4]) = *reinterpret_cast<const float4*>(&Bs[kk][tc + 4]);
            #pragma unroll
            for (int i = 0; i < 8; i++)
                #pragma unroll
                for (int j = 0; j < 8; j++)
                    acc[i][j] = fmaf(a[i], b[j], acc[i][j]);
        }
        __syncthreads();
    }

    #pragma unroll
    for (int i = 0; i < 8; i++) {
        long crow = brow0 + tr + i;
        float* cp = C + crow * (long)N + bcol0 + tc;
        #pragma unroll
        for (int j = 0; j < 8; j += 4) {
            float4 v = make_float4(acc[i][j], acc[i][j + 1], acc[i][j + 2], acc[i][j + 3]);
            if (bias) {
                const float* bb = bias + bcol0 + tc + j;
                v.x += bb[0]; v.y += bb[1]; v.z += bb[2]; v.w += bb[3];
            }
            *reinterpret_cast<float4*>(cp + j) = v;
        }
    }
}

// ---------------- conv epilogue: K-tap window sum + bias + relu + maxpool ----------------
// G[(n*32+s)][f*4+k] holds sum_e label_reps[n,s,e]*conv_w[f,e,k].
// conv output at (n,f,t) = sum_k G[(n,t+k)][f*4+k], t in [0,29).
__global__ void conv_reduce(const float* __restrict__ G, const float* __restrict__ cb,
                            float* __restrict__ lr0)
{
    int idx = blockIdx.x * 256 + threadIdx.x;   // n*512 + f
    int n = idx >> 9;
    int f = idx & 511;
    const float* g = G + (long)n * 32 * 2048 + f * 4;

    float P1 = 0.f, P2 = 0.f, P3 = 0.f;
    float best = -FLT_MAX;
    #pragma unroll
    for (int s = 0; s < 32; s++) {
        float4 q = *reinterpret_cast<const float4*>(g + (long)s * 2048);
        if (s >= 3) best = fmaxf(best, P3 + q.w);  // completes window t = s-3
        P3 = P2 + q.z;   // window t = s-2
        P2 = P1 + q.y;   // window t = s-1
        P1 = q.x;        // window t = s
    }
    // relu(v + b) then max over t == relu(max_t v + b) since b is constant in t
    lr0[idx] = fmaxf(best + cb[f], 0.f);
}

// ---------------- row softmax over L=512, one warp per row ----------------
__global__ void softmax_rows(float* __restrict__ S)
{
    int row  = blockIdx.x * 8 + (threadIdx.x >> 5);
    int lane = threadIdx.x & 31;
    float* p = S + (long)row * 512;

    float v[16];
    float m = -FLT_MAX;
    #pragma unroll
    for (int i = 0; i < 16; i++) {
        v[i] = p[lane + 32 * i];
        m = fmaxf(m, v[i]);
    }
    #pragma unroll
    for (int o = 16; o > 0; o >>= 1) m = fmaxf(m, __shfl_xor_sync(0xffffffffu, m, o));

    float s = 0.f;
    #pragma unroll
    for (int i = 0; i < 16; i++) {
        v[i] = expf(v[i] - m);
        s += v[i];
    }
    #pragma unroll
    for (int o = 16; o > 0; o >>= 1) s += __shfl_xor_sync(0xffffffffu, s, o);

    float inv = 1.f / s;
    #pragma unroll
    for (int i = 0; i < 16; i++) p[lane + 32 * i] = v[i] * inv;
}

// ---------------- launch ----------------
extern "C" void kernel_launch(void* const* d_in, const int* in_sizes, int n_in,
                              void* d_out, int out_size)
{
    const float* x      = (const float*)d_in[0];  // (16,512,512)
    const float* lreps  = (const float*)d_in[1];  // (4096,32,300)
    const float* conv_w = (const float*)d_in[2];  // (512,300,4)
    const float* conv_b = (const float*)d_in[3];  // (512)
    const float* lin_w  = (const float*)d_in[4];  // (512,512)
    const float* lin_b  = (const float*)d_in[5];  // (512)
    float* out = (float*)d_out;                   // (16,4096,512)

    float *G, *Wt, *linT, *xT, *lr0, *lr;
    cudaGetSymbolAddress((void**)&G,    g_G);
    cudaGetSymbolAddress((void**)&Wt,   g_Wt);
    cudaGetSymbolAddress((void**)&linT, g_linT);
    cudaGetSymbolAddress((void**)&xT,   g_xT);
    cudaGetSymbolAddress((void**)&lr0,  g_lr0);
    cudaGetSymbolAddress((void**)&lr,   g_lr);

    // prep transposes
    k_prep_w<<<(614400 + 255) / 256, 256>>>(conv_w, lin_w);
    k_prep_x<<<(16 * 512 * 512) / 256, 256>>>(x);

    // conv as GEMM: (131072 x 300) @ (300 x 2048) -> G
    {
        dim3 grid(2048 / 128, 131072 / 128, 1);
        sgemm128<<<grid, 256>>>(lreps, Wt, G, nullptr, 131072, 2048, 300, 0, 0, 0);
    }

    // window-sum + bias + relu + maxpool -> lr0 (4096 x 512)
    conv_reduce<<<(4096 * 512) / 256, 256>>>(G, conv_b, lr0);

    // linear: lr = lr0 @ lin_w^T + lin_b
    {
        dim3 grid(512 / 128, 4096 / 128, 1);
        sgemm128<<<grid, 256>>>(lr0, linT, lr, lin_b, 4096, 512, 512, 0, 0, 0);
    }

    // attention logits per batch: S[b] = lr @ xT[b]   (4096 x 512)
    {
        dim3 grid(512 / 128, 4096 / 128, 16);
        sgemm128<<<grid, 256>>>(lr, xT, G, nullptr, 4096, 512, 512,
                                0, 262144, 2097152);
    }

    // softmax over L for all 16*4096 rows
    softmax_rows<<<(16 * 4096) / 8, 256>>>(G);

    // out[b] = P[b] @ x[b]   (4096 x 512)
    {
        dim3 grid(512 / 128, 4096 / 128, 16);
        sgemm128<<<grid, 256>>>(G, x, out, nullptr, 4096, 512, 512,
                                2097152, 262144, 2097152);
    }
}

// round 5
// speedup vs baseline: 1.0536x; 1.0536x over previous
#include <cuda_runtime.h>
#include <math.h>
#include <cfloat>

// Problem constants
// x: (16, 512, 512)  label_reps: (4096, 32, 300)  conv_w: (512, 300, 4)
// conv_b: (512)  lin_w: (512, 512)  lin_b: (512)  label_length: (4096) unused
// out: (16, 4096, 512) float32

// ---------------- scratch (static device memory; no allocation) ----------------
// G: conv GEMM output (131072 x 2048) = 1.07 GB, later reused for attention S (16*4096*512)
__device__ float g_G[(size_t)131072 * 2048];
__device__ float g_Wt[300 * 2048];        // Wt[e][f*4+k] = conv_w[f][e][k]
__device__ float g_linT[512 * 512];       // linT[c][f] = lin_w[f][c]
__device__ float g_xT[16 * 512 * 512];    // xT[b][f][l] = x[b][l][f]
__device__ float g_lr0[4096 * 512];       // conv+relu+maxpool output
__device__ float g_lr[4096 * 512];        // after linear

// ---------------- prep: weight transposes ----------------
__global__ void k_prep_w(const float* __restrict__ conv_w, const float* __restrict__ lin_w)
{
    int i = blockIdx.x * 256 + threadIdx.x;
    if (i < 614400) {
        int e = i / 2048;
        int r = i - e * 2048;
        int f = r >> 2;
        int k = r & 3;
        g_Wt[i] = conv_w[f * 1200 + e * 4 + k];
    }
    if (i < 262144) {
        int c = i >> 9;
        int f = i & 511;
        g_linT[i] = lin_w[f * 512 + c];
    }
}

// ---------------- prep: transpose x to (b, f, l) ----------------
__global__ void k_prep_x(const float* __restrict__ x)
{
    int i = blockIdx.x * 256 + threadIdx.x;   // grid covers 16*512*512
    int b = i >> 18;
    int r = i & 262143;
    int f = r >> 9;
    int l = r & 511;
    g_xT[i] = x[b * 262144 + l * 512 + f];
}

// ---------------- classic 128x128x8 fp32 GEMM, 256 thr, 8x8 per thread ----------------
// C = A(MxK, row-major) * B(KxN, row-major) [+ bias broadcast over rows]
// Requires M % 128 == 0, N % 128 == 0 (true for all call sites). K arbitrary.
// blockIdx.z batches with element strides sA/sB/sC.
__global__ __launch_bounds__(256, 2)
void sgemm128(const float* __restrict__ Abase, const float* __restrict__ Bbase,
              float* __restrict__ Cbase, const float* __restrict__ bias,
              int M, int N, int K, long sA, long sB, long sC)
{
    const float* A = Abase + (long)blockIdx.z * sA;
    const float* Bp = Bbase + (long)blockIdx.z * sB;
    float*       C = Cbase + (long)blockIdx.z * sC;

    __shared__ float As[8][128];   // A tile, stored transposed: As[k][m]
    __shared__ float Bs[8][128];   // Bs[k][n]

    const int tid = threadIdx.x;
    const long brow0 = (long)blockIdx.y * 128;
    const int  bcol0 = blockIdx.x * 128;

    // A-tile load map: 128 rows x 8 cols, 4 scalars per thread (K may be unaligned)
    const int la_r = tid >> 1;
    const int la_c = (tid & 1) << 2;
    // B-tile load map: 8 rows x 128 cols, one float4 per thread
    const int lb_r = tid >> 5;
    const int lb_c = (tid & 31) << 2;

    // compute map: 16x16 threads, each 8x8
    const int tr = (tid >> 4) << 3;
    const int tc = (tid & 15) << 3;

    float acc[8][8];
    #pragma unroll
    for (int i = 0; i < 8; i++)
        #pragma unroll
        for (int j = 0; j < 8; j++)
            acc[i][j] = 0.f;

    const float* Arow = A + (brow0 + la_r) * (long)K;

    for (int k0 = 0; k0 < K; k0 += 8) {
        #pragma unroll
        for (int j = 0; j < 4; j++) {
            int kk = k0 + la_c + j;
            As[la_c + j][la_r] = (kk < K) ? Arow[kk] : 0.f;
        }
        {
            int kb = k0 + lb_r;
            float4 bv = make_float4(0.f, 0.f, 0.f, 0.f);
            if (kb < K)
                bv = *reinterpret_cast<const float4*>(Bp + (long)kb * N + bcol0 + lb_c);
            *reinterpret_cast<float4*>(&Bs[lb_r][lb_c]) = bv;
        }
        __syncthreads();

        #pragma unroll
        for (int kk = 0; kk < 8; kk++) {
            float a[8], b[8];
            *reinterpret_cast<float4*>(&a[0]) = *reinterpret_cast<const float4*>(&As[kk][tr]);
            *reinterpret_cast<float4*>(&a[4]) = *reinterpret_cast<const float4*>(&As[kk][tr + 4]);
            *reinterpret_cast<float4*>(&b[0]) = *reinterpret_cast<const float4*>(&Bs[kk][tc]);
            *reinterpret_cast<float4*>(&b[4]) = *reinterpret_cast<const float4*>(&Bs[kk][tc + 4]);
            #pragma unroll
            for (int i = 0; i < 8; i++)
                #pragma unroll
                for (int j = 0; j < 8; j++)
                    acc[i][j] = fmaf(a[i], b[j], acc[i][j]);
        }
        __syncthreads();
    }

    #pragma unroll
    for (int i = 0; i < 8; i++) {
        long crow = brow0 + tr + i;
        float* cp = C + crow * (long)N + bcol0 + tc;
        #pragma unroll
        for (int j = 0; j < 8; j += 4) {
            float4 v = make_float4(acc[i][j], acc[i][j + 1], acc[i][j + 2], acc[i][j + 3]);
            if (bias) {
                const float* bb = bias + bcol0 + tc + j;
                v.x += bb[0]; v.y += bb[1]; v.z += bb[2]; v.w += bb[3];
            }
            *reinterpret_cast<float4*>(cp + j) = v;
        }
    }
}

// ---------------- conv epilogue: K-tap window sum + bias + relu + maxpool ----------------
// G[(n*32+s)][f*4+k] holds sum_e label_reps[n,s,e]*conv_w[f,e,k].
// conv output at (n,f,t) = sum_k G[(n,t+k)][f*4+k], t in [0,29).
__global__ void conv_reduce(const float* __restrict__ G, const float* __restrict__ cb,
                            float* __restrict__ lr0)
{
    int idx = blockIdx.x * 256 + threadIdx.x;   // n*512 + f
    int n = idx >> 9;
    int f = idx & 511;
    const float* g = G + (long)n * 32 * 2048 + f * 4;

    float P1 = 0.f, P2 = 0.f, P3 = 0.f;
    float best = -FLT_MAX;
    #pragma unroll
    for (int s = 0; s < 32; s++) {
        float4 q = *reinterpret_cast<const float4*>(g + (long)s * 2048);
        if (s >= 3) best = fmaxf(best, P3 + q.w);  // completes window t = s-3
        P3 = P2 + q.z;   // window t = s-2
        P2 = P1 + q.y;   // window t = s-1
        P1 = q.x;        // window t = s
    }
    // relu(v + b) then max over t == relu(max_t v + b) since b is constant in t
    lr0[idx] = fmaxf(best + cb[f], 0.f);
}

// ---------------- row softmax over L=512, one warp per row ----------------
__global__ void softmax_rows(float* __restrict__ S)
{
    int row  = blockIdx.x * 8 + (threadIdx.x >> 5);
    int lane = threadIdx.x & 31;
    float* p = S + (long)row * 512;

    float v[16];
    float m = -FLT_MAX;
    #pragma unroll
    for (int i = 0; i < 16; i++) {
        v[i] = p[lane + 32 * i];
        m = fmaxf(m, v[i]);
    }
    #pragma unroll
    for (int o = 16; o > 0; o >>= 1) m = fmaxf(m, __shfl_xor_sync(0xffffffffu, m, o));

    float s = 0.f;
    #pragma unroll
    for (int i = 0; i < 16; i++) {
        v[i] = expf(v[i] - m);
        s += v[i];
    }
    #pragma unroll
    for (int o = 16; o > 0; o >>= 1) s += __shfl_xor_sync(0xffffffffu, s, o);

    float inv = 1.f / s;
    #pragma unroll
    for (int i = 0; i < 16; i++) p[lane + 32 * i] = v[i] * inv;
}

// ---------------- launch ----------------
extern "C" void kernel_launch(void* const* d_in, const int* in_sizes, int n_in,
                              void* d_out, int out_size)
{
    const float* x      = (const float*)d_in[0];  // (16,512,512)
    const float* lreps  = (const float*)d_in[1];  // (4096,32,300)
    const float* conv_w = (const float*)d_in[2];  // (512,300,4)
    const float* conv_b = (const float*)d_in[3];  // (512)
    const float* lin_w  = (const float*)d_in[4];  // (512,512)
    const float* lin_b  = (const float*)d_in[5];  // (512)
    float* out = (float*)d_out;                   // (16,4096,512)

    float *G, *Wt, *linT, *xT, *lr0, *lr;
    cudaGetSymbolAddress((void**)&G,    g_G);
    cudaGetSymbolAddress((void**)&Wt,   g_Wt);
    cudaGetSymbolAddress((void**)&linT, g_linT);
    cudaGetSymbolAddress((void**)&xT,   g_xT);
    cudaGetSymbolAddress((void**)&lr0,  g_lr0);
    cudaGetSymbolAddress((void**)&lr,   g_lr);

    // prep transposes
    k_prep_w<<<(614400 + 255) / 256, 256>>>(conv_w, lin_w);
    k_prep_x<<<(16 * 512 * 512) / 256, 256>>>(x);

    // conv as GEMM: (131072 x 300) @ (300 x 2048) -> G
    {
        dim3 grid(2048 / 128, 131072 / 128, 1);
        sgemm128<<<grid, 256>>>(lreps, Wt, G, nullptr, 131072, 2048, 300, 0, 0, 0);
    }

    // window-sum + bias + relu + maxpool -> lr0 (4096 x 512)
    conv_reduce<<<(4096 * 512) / 256, 256>>>(G, conv_b, lr0);

    // linear: lr = lr0 @ lin_w^T + lin_b
    {
        dim3 grid(512 / 128, 4096 / 128, 1);
        sgemm128<<<grid, 256>>>(lr0, linT, lr, lin_b, 4096, 512, 512, 0, 0, 0);
    }

    // attention logits per batch: S[b] = lr @ xT[b]   (4096 x 512)
    {
        dim3 grid(512 / 128, 4096 / 128, 16);
        sgemm128<<<grid, 256>>>(lr, xT, G, nullptr, 4096, 512, 512,
                                0, 262144, 2097152);
    }

    // softmax over L for all 16*4096 rows
    softmax_rows<<<(16 * 4096) / 8, 256>>>(G);

    // out[b] = P[b] @ x[b]   (4096 x 512)
    {
        dim3 grid(512 / 128, 4096 / 128, 16);
        sgemm128<<<grid, 256>>>(G, x, out, nullptr, 4096, 512, 512,
                                2097152, 262144, 2097152);
    }
}

// round 7
// speedup vs baseline: 3.5304x; 3.3507x over previous
#include <cuda_runtime.h>
#include <cuda_bf16.h>
#include <math.h>
#include <cfloat>
#include <cstdint>

typedef __nv_bfloat16 bf16;

// ============================================================================
// x(16,512,512) reps(4096,32,300) conv_w(512,300,4) conv_b(512)
// lin_w(512,512) lin_b(512) -> out(16,4096,512) fp32
// GEMMs via mma.sync.m16n8k16 bf16 (baseline PTX — no 'a' features),
// 3-term split precision: hi*hi + hi*lo + lo*hi, fp32 accumulators.
// ============================================================================

// ---------------- static scratch ----------------
__device__ __align__(16) bf16 g_Ah[131072L * 320];   // conv A hi (K padded 300->320)
__device__ __align__(16) bf16 g_Al[131072L * 320];   // conv A lo
__device__ __align__(16) bf16 g_Bh[2048 * 320];      // conv B: [c=f*4+k][e]
__device__ __align__(16) bf16 g_Bl[2048 * 320];
__device__ __align__(16) bf16 g_lnh[512 * 512];      // lin_w [f][c] (native = B layout)
__device__ __align__(16) bf16 g_lnl[512 * 512];
__device__ __align__(16) bf16 g_xh[16L * 512 * 512]; // x elementwise (B of logits)
__device__ __align__(16) bf16 g_xl[16L * 512 * 512];
__device__ __align__(16) bf16 g_xTh[16L * 512 * 512];// xT[b][f][l] (B of out-GEMM)
__device__ __align__(16) bf16 g_xTl[16L * 512 * 512];
__device__ __align__(16) bf16 g_r0h[4096 * 512];     // conv+pool+relu out hi/lo
__device__ __align__(16) bf16 g_r0l[4096 * 512];
__device__ __align__(16) bf16 g_rh[4096 * 512];      // after linear hi/lo
__device__ __align__(16) bf16 g_rl[4096 * 512];
__device__ float g_S[16L * 4096 * 512];              // logits fp32
__device__ __align__(16) bf16 g_Sh[16L * 4096 * 512];// softmax probs hi/lo
__device__ __align__(16) bf16 g_Sl[16L * 4096 * 512];

// ---------------- helpers ----------------
__device__ __forceinline__ uint32_t smem_u32(const void* p) {
    uint32_t a;
    asm("{ .reg .u64 t; cvta.to.shared.u64 t, %1; cvt.u32.u64 %0, t; }" : "=r"(a) : "l"(p));
    return a;
}
__device__ __forceinline__ void cpasync16(uint32_t dst, const void* src) {
    asm volatile("cp.async.cg.shared.global [%0], [%1], 16;" :: "r"(dst), "l"(src) : "memory");
}
#define CP_COMMIT() asm volatile("cp.async.commit_group;" ::: "memory")
#define CP_WAIT1()  asm volatile("cp.async.wait_group 1;" ::: "memory")
#define CP_WAIT0()  asm volatile("cp.async.wait_group 0;" ::: "memory")

__device__ __forceinline__ void ldsm4(uint32_t* r, uint32_t addr) {
    asm volatile("ldmatrix.sync.aligned.m8n8.x4.shared.b16 {%0,%1,%2,%3}, [%4];"
                 : "=r"(r[0]), "=r"(r[1]), "=r"(r[2]), "=r"(r[3]) : "r"(addr));
}
__device__ __forceinline__ void mma16816(float* c, const uint32_t* a, const uint32_t* b) {
    asm volatile("mma.sync.aligned.m16n8k16.row.col.f32.bf16.bf16.f32 "
        "{%0,%1,%2,%3}, {%4,%5,%6,%7}, {%8,%9}, {%0,%1,%2,%3};"
        : "+f"(c[0]), "+f"(c[1]), "+f"(c[2]), "+f"(c[3])
        : "r"(a[0]), "r"(a[1]), "r"(a[2]), "r"(a[3]), "r"(b[0]), "r"(b[1]));
}
__device__ __forceinline__ uint32_t swz(uint32_t off) { return off ^ ((off >> 3) & 0x70); }
__device__ __forceinline__ void split(float v, bf16* h, bf16* l) {
    bf16 hh = __float2bfloat16(v);
    *h = hh;
    *l = __float2bfloat16(v - __bfloat162float(hh));
}

// ---------------- GEMM: D(128x128) = A(128xK) . B(128xK)^T, 3-term bf16 split ----------------
// 8 warps as 2(M) x 4(N); warp tile 64x32; K-tile 64; 2-stage cp.async pipeline.
// EPI 0: store fp32 C   EPI 1: +bias, split -> Eh/El   EPI 2: conv window+pool+relu -> Eh/El
static constexpr int STG_BYTES = 65536;                // 4 tiles (Ah,Al,Bh,Bl) x 16KB
static constexpr int SMEMSZ = 2 * STG_BYTES;           // 131072 (EPI2 buf reuses stage 0+)

template <int EPI>
__global__ void __launch_bounds__(256, 1)
mmagemm(const bf16* __restrict__ Ah, const bf16* __restrict__ Al,
        const bf16* __restrict__ Bh, const bf16* __restrict__ Bl,
        int K, long sA, long sB,
        float* __restrict__ C, long sC, int ldc,
        const float* __restrict__ bias,
        bf16* __restrict__ Eh, bf16* __restrict__ El)
{
    extern __shared__ char smem[];
    const uint32_t sb = smem_u32(smem);
    const int tid = threadIdx.x, wid = tid >> 5, lane = tid & 31;
    const int wm0 = (wid >> 2) * 64;       // warp row offset in tile
    const int wn0 = (wid & 3) * 32;        // warp col offset in tile
    const long z = blockIdx.z;
    const bf16* pA[2] = { Ah + z * sA, Al + z * sA };
    const bf16* pB[2] = { Bh + z * sB, Bl + z * sB };
    const long m0 = (long)blockIdx.y * 128;
    const int  n0 = blockIdx.x * 128;
    const int  KT = K >> 6;

    float acc[4][4][4];
    #pragma unroll
    for (int mi = 0; mi < 4; mi++)
        #pragma unroll
        for (int ni = 0; ni < 4; ni++)
            #pragma unroll
            for (int r = 0; r < 4; r++)
                acc[mi][ni][r] = 0.f;

    // stage loader: 4 tiles (Ah, Al, Bh, Bl), each 128 rows x 64 bf16 (128B), SW128
    auto load_stage = [&](int s, int k0) {
        const bf16* src[4] = { pA[0] + m0 * K + k0, pA[1] + m0 * K + k0,
                               pB[0] + (long)n0 * K + k0, pB[1] + (long)n0 * K + k0 };
        uint32_t base = sb + s * STG_BYTES;
        #pragma unroll
        for (int t = 0; t < 4; t++) {
            uint32_t tb = base + t * 16384;
            const bf16* sp = src[t];
            #pragma unroll
            for (int i = 0; i < 4; i++) {
                int chunk = tid + i * 256;          // 0..1023
                int row = chunk >> 3, c16 = chunk & 7;
                cpasync16(tb + swz(row * 128 + c16 * 16), sp + (long)row * K + c16 * 8);
            }
        }
    };

    load_stage(0, 0); CP_COMMIT();
    load_stage(1, 64); CP_COMMIT();

    for (int kt = 0; kt < KT; kt++) {
        if (kt + 1 < KT) { CP_WAIT1(); } else { CP_WAIT0(); }
        __syncthreads();
        const uint32_t st = sb + (kt & 1) * STG_BYTES;

        #pragma unroll
        for (int kk = 0; kk < 4; kk++) {
            uint32_t a_h[4][4], a_l[4][4], b_h[4][2], b_l[4][2];
            // A fragments (row-major m16k16, ldmatrix.x4)
            #pragma unroll
            for (int mi = 0; mi < 4; mi++) {
                uint32_t off = (uint32_t)(wm0 + mi * 16 + (lane & 15)) * 128
                             + kk * 32 + (lane >> 4) * 16;
                ldsm4(a_h[mi], st + swz(off));               // Ah tile @ +0
                ldsm4(a_l[mi], st + 16384 + swz(off));       // Al tile
            }
            // B fragments ([n][k] storage = K x N col-major), 2 n-octs per ldmatrix.x4
            #pragma unroll
            for (int q = 0; q < 2; q++) {
                uint32_t off = (uint32_t)(wn0 + q * 16 + (lane >> 4) * 8 + (lane & 7)) * 128
                             + kk * 32 + ((lane >> 3) & 1) * 16;
                uint32_t r[4];
                ldsm4(r, st + 32768 + swz(off));             // Bh tile
                b_h[2 * q][0] = r[0]; b_h[2 * q][1] = r[1];
                b_h[2 * q + 1][0] = r[2]; b_h[2 * q + 1][1] = r[3];
                ldsm4(r, st + 49152 + swz(off));             // Bl tile
                b_l[2 * q][0] = r[0]; b_l[2 * q][1] = r[1];
                b_l[2 * q + 1][0] = r[2]; b_l[2 * q + 1][1] = r[3];
            }
            // 3 terms: hi*hi, hi*lo, lo*hi
            #pragma unroll
            for (int mi = 0; mi < 4; mi++)
                #pragma unroll
                for (int ni = 0; ni < 4; ni++) {
                    mma16816(acc[mi][ni], a_h[mi], b_h[ni]);
                    mma16816(acc[mi][ni], a_h[mi], b_l[ni]);
                    mma16816(acc[mi][ni], a_l[mi], b_h[ni]);
                }
        }
        __syncthreads();
        if (kt + 2 < KT) { load_stage(kt & 1, (kt + 2) * 64); CP_COMMIT(); }
    }

    // -------- epilogue --------
    // acc element (mi,ni,r): row = wm0+mi*16+(lane>>2)+(r>>1)*8, col = wn0+ni*8+(lane&3)*2+(r&1)
    if (EPI == 0) {
        #pragma unroll
        for (int mi = 0; mi < 4; mi++)
            #pragma unroll
            for (int ni = 0; ni < 4; ni++) {
                long row = m0 + wm0 + mi * 16 + (lane >> 2);
                int  col = n0 + wn0 + ni * 8 + (lane & 3) * 2;
                float* cp = C + z * sC + row * (long)ldc + col;
                *reinterpret_cast<float2*>(cp) =
                    make_float2(acc[mi][ni][0], acc[mi][ni][1]);
                *reinterpret_cast<float2*>(cp + 8L * ldc) =
                    make_float2(acc[mi][ni][2], acc[mi][ni][3]);
            }
    } else if (EPI == 1) {
        #pragma unroll
        for (int mi = 0; mi < 4; mi++)
            #pragma unroll
            for (int ni = 0; ni < 4; ni++) {
                long row = m0 + wm0 + mi * 16 + (lane >> 2);
                int  col = n0 + wn0 + ni * 8 + (lane & 3) * 2;
                #pragma unroll
                for (int r = 0; r < 4; r++) {
                    long rr = row + (r >> 1) * 8;
                    int  cc = col + (r & 1);
                    float v = acc[mi][ni][r] + bias[cc];
                    bf16 h, l; split(v, &h, &l);
                    Eh[rr * 512 + cc] = h;
                    El[rr * 512 + cc] = l;
                }
            }
    } else {
        // stage acc tile to smem (fp32, pitch 132), then window-sum/pool/relu
        float* buf = reinterpret_cast<float*>(smem);
        #pragma unroll
        for (int mi = 0; mi < 4; mi++)
            #pragma unroll
            for (int ni = 0; ni < 4; ni++) {
                int row = wm0 + mi * 16 + (lane >> 2);
                int col = wn0 + ni * 8 + (lane & 3) * 2;
                *reinterpret_cast<float2*>(buf + row * 132 + col) =
                    make_float2(acc[mi][ni][0], acc[mi][ni][1]);
                *reinterpret_cast<float2*>(buf + (row + 8) * 132 + col) =
                    make_float2(acc[mi][ni][2], acc[mi][ni][3]);
            }
        __syncthreads();
        if (tid < 128) {
            int lab = tid >> 5, f = tid & 31;
            const float* g = buf + (lab * 32) * 132 + f * 4;
            float P1 = 0.f, P2 = 0.f, P3 = 0.f, best = -FLT_MAX;
            #pragma unroll
            for (int s = 0; s < 32; s++) {
                float q0 = g[s * 132 + 0], q1 = g[s * 132 + 1];
                float q2 = g[s * 132 + 2], q3 = g[s * 132 + 3];
                if (s >= 3) best = fmaxf(best, P3 + q3);   // completes window t = s-3
                P3 = P2 + q2;
                P2 = P1 + q1;
                P1 = q0;
            }
            int  fg  = (n0 >> 2) + f;                      // global filter
            long lab_g = (m0 >> 5) + lab;                  // global label
            float v = fmaxf(best + bias[fg], 0.f);
            bf16 h, l; split(v, &h, &l);
            Eh[lab_g * 512 + fg] = h;
            El[lab_g * 512 + fg] = l;
        }
    }
}

// ---------------- prep kernels ----------------
__global__ void k_prep_A(const float* __restrict__ reps) {
    long row = blockIdx.x; int k = threadIdx.x;          // 320 threads
    float v = (k < 300) ? reps[row * 300 + k] : 0.f;
    bf16 h, l; split(v, &h, &l);
    g_Ah[row * 320 + k] = h;
    g_Al[row * 320 + k] = l;
}
__global__ void k_prep_B(const float* __restrict__ cw) {
    int c = blockIdx.x, e = threadIdx.x;                 // 2048 x 320
    int f = c >> 2, k = c & 3;
    float v = (e < 300) ? cw[f * 1200 + e * 4 + k] : 0.f;
    bf16 h, l; split(v, &h, &l);
    g_Bh[c * 320 + e] = h;
    g_Bl[c * 320 + e] = l;
}
__global__ void k_prep_lin(const float* __restrict__ lw) {
    int i = blockIdx.x * 512 + threadIdx.x;              // 512 x 512
    bf16 h, l; split(lw[i], &h, &l);
    g_lnh[i] = h;  g_lnl[i] = l;
}
__global__ void k_prep_xe(const float* __restrict__ x) {
    long i = (long)blockIdx.x * 256 + threadIdx.x;       // 16*512*512
    bf16 h, l; split(x[i], &h, &l);
    g_xh[i] = h;  g_xl[i] = l;
}
__global__ void k_prep_xT(const float* __restrict__ x) {
    __shared__ float t[32][33];
    int b = blockIdx.z, l0 = blockIdx.x * 32, f0 = blockIdx.y * 32;
    int tx = threadIdx.x, ty = threadIdx.y;              // (32, 8)
    long base = (long)b * 262144;
    #pragma unroll
    for (int j = 0; j < 4; j++)
        t[ty + 8 * j][tx] = x[base + (long)(l0 + ty + 8 * j) * 512 + f0 + tx];
    __syncthreads();
    #pragma unroll
    for (int j = 0; j < 4; j++) {
        float v = t[tx][ty + 8 * j];                     // = x[b][l0+tx][f0+ty+8j]
        bf16 h, l; split(v, &h, &l);
        long o = base + (long)(f0 + ty + 8 * j) * 512 + l0 + tx;
        g_xTh[o] = h;  g_xTl[o] = l;
    }
}
// ---------------- softmax over L=512, warp per row, emits hi/lo probs ----------------
__global__ void k_softmax(const float* __restrict__ S) {
    long row = (long)blockIdx.x * 8 + (threadIdx.x >> 5);
    int lane = threadIdx.x & 31;
    const float* p = S + row * 512;
    float v[16], m = -FLT_MAX;
    #pragma unroll
    for (int i = 0; i < 16; i++) { v[i] = p[lane + 32 * i]; m = fmaxf(m, v[i]); }
    #pragma unroll
    for (int o = 16; o > 0; o >>= 1) m = fmaxf(m, __shfl_xor_sync(0xffffffffu, m, o));
    float s = 0.f;
    #pragma unroll
    for (int i = 0; i < 16; i++) { v[i] = expf(v[i] - m); s += v[i]; }
    #pragma unroll
    for (int o = 16; o > 0; o >>= 1) s += __shfl_xor_sync(0xffffffffu, s, o);
    float inv = 1.f / s;
    #pragma unroll
    for (int i = 0; i < 16; i++) {
        float q = v[i] * inv;
        bf16 h, l; split(q, &h, &l);
        g_Sh[row * 512 + lane + 32 * i] = h;
        g_Sl[row * 512 + lane + 32 * i] = l;
    }
}

// ---------------- launch ----------------
extern "C" void kernel_launch(void* const* d_in, const int* in_sizes, int n_in,
                              void* d_out, int out_size)
{
    const float* x      = (const float*)d_in[0];
    const float* reps   = (const float*)d_in[1];
    const float* conv_w = (const float*)d_in[2];
    const float* conv_b = (const float*)d_in[3];
    const float* lin_w  = (const float*)d_in[4];
    const float* lin_b  = (const float*)d_in[5];
    float* out = (float*)d_out;

    cudaFuncSetAttribute(mmagemm<0>, cudaFuncAttributeMaxDynamicSharedMemorySize, SMEMSZ);
    cudaFuncSetAttribute(mmagemm<1>, cudaFuncAttributeMaxDynamicSharedMemorySize, SMEMSZ);
    cudaFuncSetAttribute(mmagemm<2>, cudaFuncAttributeMaxDynamicSharedMemorySize, SMEMSZ);

    bf16 *Ah, *Al, *Bh, *Bl, *lnh, *lnl, *xh, *xl, *xTh, *xTl, *r0h, *r0l, *rh, *rl, *Sh, *Sl;
    float* S;
    cudaGetSymbolAddress((void**)&Ah, g_Ah);   cudaGetSymbolAddress((void**)&Al, g_Al);
    cudaGetSymbolAddress((void**)&Bh, g_Bh);   cudaGetSymbolAddress((void**)&Bl, g_Bl);
    cudaGetSymbolAddress((void**)&lnh, g_lnh); cudaGetSymbolAddress((void**)&lnl, g_lnl);
    cudaGetSymbolAddress((void**)&xh, g_xh);   cudaGetSymbolAddress((void**)&xl, g_xl);
    cudaGetSymbolAddress((void**)&xTh, g_xTh); cudaGetSymbolAddress((void**)&xTl, g_xTl);
    cudaGetSymbolAddress((void**)&r0h, g_r0h); cudaGetSymbolAddress((void**)&r0l, g_r0l);
    cudaGetSymbolAddress((void**)&rh, g_rh);   cudaGetSymbolAddress((void**)&rl, g_rl);
    cudaGetSymbolAddress((void**)&Sh, g_Sh);   cudaGetSymbolAddress((void**)&Sl, g_Sl);
    cudaGetSymbolAddress((void**)&S, g_S);

    // operand prep
    k_prep_A<<<131072, 320>>>(reps);
    k_prep_B<<<2048, 320>>>(conv_w);
    k_prep_lin<<<512, 512>>>(lin_w);
    k_prep_xe<<<(16 * 512 * 512) / 256, 256>>>(x);
    k_prep_xT<<<dim3(16, 16, 16), dim3(32, 8)>>>(x);

    // conv GEMM (131072 x 2048, K=320) with fused window+pool+relu epilogue -> r0
    mmagemm<2><<<dim3(16, 1024, 1), 256, SMEMSZ>>>(
        Ah, Al, Bh, Bl, 320, 0, 0, nullptr, 0, 0, conv_b, r0h, r0l);

    // linear (4096 x 512, K=512) + bias -> r (split)
    mmagemm<1><<<dim3(4, 32, 1), 256, SMEMSZ>>>(
        r0h, r0l, lnh, lnl, 512, 0, 0, nullptr, 0, 0, lin_b, rh, rl);

    // logits per batch: S[b] = r @ x[b]^T  (4096 x 512)
    mmagemm<0><<<dim3(4, 32, 16), 256, SMEMSZ>>>(
        rh, rl, xh, xl, 512, 0, 262144, S, 2097152, 512, nullptr, nullptr, nullptr);

    // softmax -> probs (split)
    k_softmax<<<(16 * 4096) / 8, 256>>>(S);

    // out[b] = P[b] @ x[b]  (4096 x 512)
    mmagemm<0><<<dim3(4, 32, 16), 256, SMEMSZ>>>(
        Sh, Sl, xTh, xTl, 512, 2097152, 262144, out, 2097152, 512, nullptr, nullptr, nullptr);
}

// round 10
// speedup vs baseline: 3.6951x; 1.0467x over previous
#include <cuda_runtime.h>
#include <cuda_bf16.h>
#include <math.h>
#include <cfloat>
#include <cstdint>

typedef __nv_bfloat16 bf16;

// ============================================================================
// x(16,512,512) reps(4096,32,300) conv_w(512,300,4) conv_b(512)
// lin_w(512,512) lin_b(512) -> out(16,4096,512) fp32
// GEMMs via mma.sync.m16n8k16 bf16 (baseline PTX), 3-term split precision:
// hi*hi + hi*lo + lo*hi, fp32 accumulators. CTA tile 128x256, warp tile 64x64.
// ============================================================================

// ---------------- static scratch ----------------
__device__ __align__(16) bf16 g_Ah[131072L * 320];   // conv A hi (K padded 300->320)
__device__ __align__(16) bf16 g_Al[131072L * 320];   // conv A lo
__device__ __align__(16) bf16 g_Bh[2048 * 320];      // conv B: [c=f*4+k][e]
__device__ __align__(16) bf16 g_Bl[2048 * 320];
__device__ __align__(16) bf16 g_lnh[512 * 512];      // lin_w [f][c] (native = B layout)
__device__ __align__(16) bf16 g_lnl[512 * 512];
__device__ __align__(16) bf16 g_xh[16L * 512 * 512]; // x elementwise (B of logits)
__device__ __align__(16) bf16 g_xl[16L * 512 * 512];
__device__ __align__(16) bf16 g_xTh[16L * 512 * 512];// xT[b][f][l] (B of out-GEMM)
__device__ __align__(16) bf16 g_xTl[16L * 512 * 512];
__device__ __align__(16) bf16 g_r0h[4096 * 512];     // conv+pool+relu out hi/lo
__device__ __align__(16) bf16 g_r0l[4096 * 512];
__device__ __align__(16) bf16 g_rh[4096 * 512];      // after linear hi/lo
__device__ __align__(16) bf16 g_rl[4096 * 512];
__device__ float g_S[16L * 4096 * 512];              // logits fp32
__device__ __align__(16) bf16 g_Sh[16L * 4096 * 512];// softmax probs hi/lo
__device__ __align__(16) bf16 g_Sl[16L * 4096 * 512];

// ---------------- helpers ----------------
__device__ __forceinline__ uint32_t smem_u32(const void* p) {
    uint32_t a;
    asm("{ .reg .u64 t; cvta.to.shared.u64 t, %1; cvt.u32.u64 %0, t; }" : "=r"(a) : "l"(p));
    return a;
}
__device__ __forceinline__ void cpasync16(uint32_t dst, const void* src) {
    asm volatile("cp.async.cg.shared.global [%0], [%1], 16;" :: "r"(dst), "l"(src) : "memory");
}
#define CP_COMMIT() asm volatile("cp.async.commit_group;" ::: "memory")
#define CP_WAIT1()  asm volatile("cp.async.wait_group 1;" ::: "memory")
#define CP_WAIT0()  asm volatile("cp.async.wait_group 0;" ::: "memory")

__device__ __forceinline__ void ldsm4(uint32_t* r, uint32_t addr) {
    asm volatile("ldmatrix.sync.aligned.m8n8.x4.shared.b16 {%0,%1,%2,%3}, [%4];"
                 : "=r"(r[0]), "=r"(r[1]), "=r"(r[2]), "=r"(r[3]) : "r"(addr));
}
__device__ __forceinline__ void mma16816(float* c, const uint32_t* a, const uint32_t* b) {
    asm volatile("mma.sync.aligned.m16n8k16.row.col.f32.bf16.bf16.f32 "
        "{%0,%1,%2,%3}, {%4,%5,%6,%7}, {%8,%9}, {%0,%1,%2,%3};"
        : "+f"(c[0]), "+f"(c[1]), "+f"(c[2]), "+f"(c[3])
        : "r"(a[0]), "r"(a[1]), "r"(a[2]), "r"(a[3]), "r"(b[0]), "r"(b[1]));
}
__device__ __forceinline__ uint32_t swz(uint32_t off) { return off ^ ((off >> 3) & 0x70); }
__device__ __forceinline__ void split(float v, bf16* h, bf16* l) {
    bf16 hh = __float2bfloat16(v);
    *h = hh;
    *l = __float2bfloat16(v - __bfloat162float(hh));
}

// ---------------- GEMM: D(128x256) = A(128xK) . B(256xK)^T, 3-term bf16 split ----------
// 8 warps as 2(M) x 4(N); warp tile 64x64; K-tile 64; 2-stage cp.async pipeline.
// Stage layout: Ah@0(16K) Al@16K Bh@32K(32K) Bl@64K(32K) = 96KB/stage.
// EPI 0: store fp32 C   EPI 1: +bias, split -> Eh/El   EPI 2: conv window+pool+relu
static constexpr int STG_BYTES = 98304;
static constexpr int SMEMSZ = 2 * STG_BYTES;           // 196608

template <int EPI>
__global__ void __launch_bounds__(256, 1)
mmagemm(const bf16* __restrict__ Ah, const bf16* __restrict__ Al,
        const bf16* __restrict__ Bh, const bf16* __restrict__ Bl,
        int K, long sA, long sB,
        float* __restrict__ C, long sC, int ldc,
        const float* __restrict__ bias,
        bf16* __restrict__ Eh, bf16* __restrict__ El)
{
    extern __shared__ char smem[];
    const uint32_t sb = smem_u32(smem);
    const int tid = threadIdx.x, wid = tid >> 5, lane = tid & 31;
    const int wm0 = (wid >> 2) * 64;       // warp row offset in tile
    const int wn0 = (wid & 3) * 64;        // warp col offset in tile
    const long z = blockIdx.z;
    const bf16* pA[2] = { Ah + z * sA, Al + z * sA };
    const bf16* pB[2] = { Bh + z * sB, Bl + z * sB };
    const long m0 = (long)blockIdx.y * 128;
    const int  n0 = blockIdx.x * 256;
    const int  KT = K >> 6;

    float acc[4][8][4];
    #pragma unroll
    for (int mi = 0; mi < 4; mi++)
        #pragma unroll
        for (int ni = 0; ni < 8; ni++)
            #pragma unroll
            for (int r = 0; r < 4; r++)
                acc[mi][ni][r] = 0.f;

    // stage loader
    auto load_stage = [&](int s, int k0) {
        uint32_t base = sb + s * STG_BYTES;
        #pragma unroll
        for (int t = 0; t < 2; t++) {                   // Ah, Al: 128 x 64
            const bf16* sp = pA[t] + m0 * K + k0;
            uint32_t tb = base + t * 16384;
            #pragma unroll
            for (int i = 0; i < 4; i++) {
                int chunk = tid + i * 256;              // 0..1023
                int row = chunk >> 3, c16 = chunk & 7;
                cpasync16(tb + swz(row * 128 + c16 * 16), sp + (long)row * K + c16 * 8);
            }
        }
        #pragma unroll
        for (int t = 0; t < 2; t++) {                   // Bh, Bl: 256 x 64
            const bf16* sp = pB[t] + (long)n0 * K + k0;
            uint32_t tb = base + 32768 + t * 32768;
            #pragma unroll
            for (int i = 0; i < 8; i++) {
                int chunk = tid + i * 256;              // 0..2047
                int row = chunk >> 3, c16 = chunk & 7;
                cpasync16(tb + swz(row * 128 + c16 * 16), sp + (long)row * K + c16 * 8);
            }
        }
    };

    load_stage(0, 0); CP_COMMIT();
    load_stage(1, 64); CP_COMMIT();

    for (int kt = 0; kt < KT; kt++) {
        if (kt + 1 < KT) { CP_WAIT1(); } else { CP_WAIT0(); }
        __syncthreads();
        const uint32_t st = sb + (kt & 1) * STG_BYTES;

        #pragma unroll
        for (int kk = 0; kk < 4; kk++) {
            uint32_t a_h[4][4], a_l[4][4];
            // A fragments (row-major m16k16)
            #pragma unroll
            for (int mi = 0; mi < 4; mi++) {
                uint32_t off = (uint32_t)(wm0 + mi * 16 + (lane & 15)) * 128
                             + kk * 32 + (lane >> 4) * 16;
                ldsm4(a_h[mi], st + swz(off));               // Ah
                ldsm4(a_l[mi], st + 16384 + swz(off));       // Al
            }
            // B: 4 q-groups of 16 cols; consume each pair immediately (low liveness)
            #pragma unroll
            for (int q = 0; q < 4; q++) {
                uint32_t off = (uint32_t)(wn0 + q * 16 + (lane >> 4) * 8 + (lane & 7)) * 128
                             + kk * 32 + ((lane >> 3) & 1) * 16;
                uint32_t rh[4], rl[4];
                ldsm4(rh, st + 32768 + swz(off));            // Bh
                ldsm4(rl, st + 65536 + swz(off));            // Bl
                #pragma unroll
                for (int half = 0; half < 2; half++) {
                    int ni = 2 * q + half;
                    uint32_t bh[2] = { rh[2 * half], rh[2 * half + 1] };
                    uint32_t bl[2] = { rl[2 * half], rl[2 * half + 1] };
                    #pragma unroll
                    for (int mi = 0; mi < 4; mi++) {
                        mma16816(acc[mi][ni], a_h[mi], bh);
                        mma16816(acc[mi][ni], a_h[mi], bl);
                        mma16816(acc[mi][ni], a_l[mi], bh);
                    }
                }
            }
        }
        __syncthreads();
        if (kt + 2 < KT) { load_stage(kt & 1, (kt + 2) * 64); CP_COMMIT(); }
    }

    // -------- epilogue --------
    // acc (mi,ni,r): row = wm0+mi*16+(lane>>2)+(r>>1)*8, col = wn0+ni*8+(lane&3)*2+(r&1)
    if (EPI == 0) {
        #pragma unroll
        for (int mi = 0; mi < 4; mi++)
            #pragma unroll
            for (int ni = 0; ni < 8; ni++) {
                long row = m0 + wm0 + mi * 16 + (lane >> 2);
                int  col = n0 + wn0 + ni * 8 + (lane & 3) * 2;
                float* cp = C + z * sC + row * (long)ldc + col;
                *reinterpret_cast<float2*>(cp) =
                    make_float2(acc[mi][ni][0], acc[mi][ni][1]);
                *reinterpret_cast<float2*>(cp + 8L * ldc) =
                    make_float2(acc[mi][ni][2], acc[mi][ni][3]);
            }
    } else if (EPI == 1) {
        #pragma unroll
        for (int mi = 0; mi < 4; mi++)
            #pragma unroll
            for (int ni = 0; ni < 8; ni++) {
                long row = m0 + wm0 + mi * 16 + (lane >> 2);
                int  col = n0 + wn0 + ni * 8 + (lane & 3) * 2;
                #pragma unroll
                for (int r = 0; r < 4; r++) {
                    long rr = row + (r >> 1) * 8;
                    int  cc = col + (r & 1);
                    float v = acc[mi][ni][r] + bias[cc];
                    bf16 h, l; split(v, &h, &l);
                    Eh[rr * 512 + cc] = h;
                    El[rr * 512 + cc] = l;
                }
            }
    } else {
        // stage full 128x256 fp32 tile into (reused) stage smem, pitch 260
        float* buf = reinterpret_cast<float*>(smem);
        #pragma unroll
        for (int mi = 0; mi < 4; mi++)
            #pragma unroll
            for (int ni = 0; ni < 8; ni++) {
                int row = wm0 + mi * 16 + (lane >> 2);
                int col = wn0 + ni * 8 + (lane & 3) * 2;
                *reinterpret_cast<float2*>(buf + row * 260 + col) =
                    make_float2(acc[mi][ni][0], acc[mi][ni][1]);
                *reinterpret_cast<float2*>(buf + (row + 8) * 260 + col) =
                    make_float2(acc[mi][ni][2], acc[mi][ni][3]);
            }
        __syncthreads();
        {
            int lab = tid >> 6, f = tid & 63;           // 4 labels x 64 filters
            const float* g = buf + (lab * 32) * 260 + f * 4;
            float P1 = 0.f, P2 = 0.f, P3 = 0.f, best = -FLT_MAX;
            #pragma unroll
            for (int s = 0; s < 32; s++) {
                float q0 = g[s * 260 + 0], q1 = g[s * 260 + 1];
                float q2 = g[s * 260 + 2], q3 = g[s * 260 + 3];
                if (s >= 3) best = fmaxf(best, P3 + q3);   // completes window t = s-3
                P3 = P2 + q2;
                P2 = P1 + q1;
                P1 = q0;
            }
            int  fg    = (n0 >> 2) + f;                    // global filter
            long lab_g = (m0 >> 5) + lab;                  // global label
            float v = fmaxf(best + bias[fg], 0.f);
            bf16 h, l; split(v, &h, &l);
            Eh[lab_g * 512 + fg] = h;
            El[lab_g * 512 + fg] = l;
        }
    }
}

// ---------------- prep kernels ----------------
__global__ void k_prep_A(const float* __restrict__ reps) {
    long row = blockIdx.x; int k = threadIdx.x;          // 320 threads
    float v = (k < 300) ? reps[row * 300 + k] : 0.f;
    bf16 h, l; split(v, &h, &l);
    g_Ah[row * 320 + k] = h;
    g_Al[row * 320 + k] = l;
}
__global__ void k_prep_B(const float* __restrict__ cw) {
    int c = blockIdx.x, e = threadIdx.x;                 // 2048 x 320
    int f = c >> 2, k = c & 3;
    float v = (e < 300) ? cw[f * 1200 + e * 4 + k] : 0.f;
    bf16 h, l; split(v, &h, &l);
    g_Bh[c * 320 + e] = h;
    g_Bl[c * 320 + e] = l;
}
__global__ void k_prep_lin(const float* __restrict__ lw) {
    int i = blockIdx.x * 512 + threadIdx.x;              // 512 x 512
    bf16 h, l; split(lw[i], &h, &l);
    g_lnh[i] = h;  g_lnl[i] = l;
}
// merged: direct split (xh/xl) + transposed split (xTh/xTl), one read of x
__global__ void k_prep_x(const float* __restrict__ x) {
    __shared__ float t[32][33];
    int b = blockIdx.z, l0 = blockIdx.x * 32, f0 = blockIdx.y * 32;
    int tx = threadIdx.x, ty = threadIdx.y;              // (32, 8)
    long base = (long)b * 262144;
    #pragma unroll
    for (int j = 0; j < 4; j++) {
        long o = base + (long)(l0 + ty + 8 * j) * 512 + f0 + tx;
        float v = x[o];
        t[ty + 8 * j][tx] = v;
        bf16 h, l; split(v, &h, &l);
        g_xh[o] = h;  g_xl[o] = l;
    }
    __syncthreads();
    #pragma unroll
    for (int j = 0; j < 4; j++) {
        float v = t[tx][ty + 8 * j];                     // = x[b][l0+tx][f0+ty+8j]
        bf16 h, l; split(v, &h, &l);
        long o = base + (long)(f0 + ty + 8 * j) * 512 + l0 + tx;
        g_xTh[o] = h;  g_xTl[o] = l;
    }
}
// ---------------- softmax over L=512, warp per row, emits hi/lo probs ----------------
__global__ void k_softmax(const float* __restrict__ S) {
    long row = (long)blockIdx.x * 8 + (threadIdx.x >> 5);
    int lane = threadIdx.x & 31;
    const float* p = S + row * 512;
    float v[16], m = -FLT_MAX;
    #pragma unroll
    for (int i = 0; i < 16; i++) { v[i] = p[lane + 32 * i]; m = fmaxf(m, v[i]); }
    #pragma unroll
    for (int o = 16; o > 0; o >>= 1) m = fmaxf(m, __shfl_xor_sync(0xffffffffu, m, o));
    float s = 0.f;
    #pragma unroll
    for (int i = 0; i < 16; i++) { v[i] = expf(v[i] - m); s += v[i]; }
    #pragma unroll
    for (int o = 16; o > 0; o >>= 1) s += __shfl_xor_sync(0xffffffffu, s, o);
    float inv = 1.f / s;
    #pragma unroll
    for (int i = 0; i < 16; i++) {
        float q = v[i] * inv;
        bf16 h, l; split(q, &h, &l);
        g_Sh[row * 512 + lane + 32 * i] = h;
        g_Sl[row * 512 + lane + 32 * i] = l;
    }
}

// ---------------- launch ----------------
extern "C" void kernel_launch(void* const* d_in, const int* in_sizes, int n_in,
                              void* d_out, int out_size)
{
    const float* x      = (const float*)d_in[0];
    const float* reps   = (const float*)d_in[1];
    const float* conv_w = (const float*)d_in[2];
    const float* conv_b = (const float*)d_in[3];
    const float* lin_w  = (const float*)d_in[4];
    const float* lin_b  = (const float*)d_in[5];
    float* out = (float*)d_out;

    cudaFuncSetAttribute(mmagemm<0>, cudaFuncAttributeMaxDynamicSharedMemorySize, SMEMSZ);
    cudaFuncSetAttribute(mmagemm<1>, cudaFuncAttributeMaxDynamicSharedMemorySize, SMEMSZ);
    cudaFuncSetAttribute(mmagemm<2>, cudaFuncAttributeMaxDynamicSharedMemorySize, SMEMSZ);

    bf16 *Ah, *Al, *Bh, *Bl, *lnh, *lnl, *xh, *xl, *xTh, *xTl, *r0h, *r0l, *rh, *rl, *Sh, *Sl;
    float* S;
    cudaGetSymbolAddress((void**)&Ah, g_Ah);   cudaGetSymbolAddress((void**)&Al, g_Al);
    cudaGetSymbolAddress((void**)&Bh, g_Bh);   cudaGetSymbolAddress((void**)&Bl, g_Bl);
    cudaGetSymbolAddress((void**)&lnh, g_lnh); cudaGetSymbolAddress((void**)&lnl, g_lnl);
    cudaGetSymbolAddress((void**)&xh, g_xh);   cudaGetSymbolAddress((void**)&xl, g_xl);
    cudaGetSymbolAddress((void**)&xTh, g_xTh); cudaGetSymbolAddress((void**)&xTl, g_xTl);
    cudaGetSymbolAddress((void**)&r0h, g_r0h); cudaGetSymbolAddress((void**)&r0l, g_r0l);
    cudaGetSymbolAddress((void**)&rh, g_rh);   cudaGetSymbolAddress((void**)&rl, g_rl);
    cudaGetSymbolAddress((void**)&Sh, g_Sh);   cudaGetSymbolAddress((void**)&Sl, g_Sl);
    cudaGetSymbolAddress((void**)&S, g_S);

    // operand prep
    k_prep_A<<<131072, 320>>>(reps);
    k_prep_B<<<2048, 320>>>(conv_w);
    k_prep_lin<<<512, 512>>>(lin_w);
    k_prep_x<<<dim3(16, 16, 16), dim3(32, 8)>>>(x);

    // conv GEMM (131072 x 2048, K=320) with fused window+pool+relu epilogue -> r0
    mmagemm<2><<<dim3(8, 1024, 1), 256, SMEMSZ>>>(
        Ah, Al, Bh, Bl, 320, 0, 0, nullptr, 0, 0, conv_b, r0h, r0l);

    // linear (4096 x 512, K=512) + bias -> r (split)
    mmagemm<1><<<dim3(2, 32, 1), 256, SMEMSZ>>>(
        r0h, r0l, lnh, lnl, 512, 0, 0, nullptr, 0, 0, lin_b, rh, rl);

    // logits per batch: S[b] = r @ x[b]^T  (4096 x 512)
    mmagemm<0><<<dim3(2, 32, 16), 256, SMEMSZ>>>(
        rh, rl, xh, xl, 512, 0, 262144, S, 2097152, 512, nullptr, nullptr, nullptr);

    // softmax -> probs (split)
    k_softmax<<<(16 * 4096) / 8, 256>>>(S);

    // out[b] = P[b] @ x[b]  (4096 x 512)
    mmagemm<0><<<dim3(2, 32, 16), 256, SMEMSZ>>>(
        Sh, Sl, xTh, xTl, 512, 2097152, 262144, out, 2097152, 512, nullptr, nullptr, nullptr);
}

// round 14
// speedup vs baseline: 3.6977x; 1.0007x over previous
#include <cuda_runtime.h>
#include <cuda_bf16.h>
#include <math.h>
#include <cfloat>
#include <cstdint>

typedef __nv_bfloat16 bf16;

// ============================================================================
// x(16,512,512) reps(4096,32,300) conv_w(512,300,4) conv_b(512)
// lin_w(512,512) lin_b(512) -> out(16,4096,512) fp32
// GEMMs via mma.sync.m16n8k16 bf16, 3-term split: hi*hi + hi*lo + lo*hi.
// CTA tile 128x128, warp tile 64x32, K-step 32, 2 CTAs/SM (67.6KB smem, <=128 regs).
// k-halves ring-buffered inside SW128 128B rows (conflict-free ldmatrix).
// ============================================================================

// ---------------- static scratch ----------------
__device__ __align__(16) bf16 g_Ah[131072L * 320];   // conv A hi (K padded 300->320)
__device__ __align__(16) bf16 g_Al[131072L * 320];   // conv A lo
__device__ __align__(16) bf16 g_Bh[2048 * 320];      // conv B: [c=f*4+k][e]
__device__ __align__(16) bf16 g_Bl[2048 * 320];
__device__ __align__(16) bf16 g_lnh[512 * 512];      // lin_w [f][c] (native = B layout)
__device__ __align__(16) bf16 g_lnl[512 * 512];
__device__ __align__(16) bf16 g_xh[16L * 512 * 512]; // x elementwise (B of logits)
__device__ __align__(16) bf16 g_xl[16L * 512 * 512];
__device__ __align__(16) bf16 g_xTh[16L * 512 * 512];// xT[b][f][l] (B of out-GEMM)
__device__ __align__(16) bf16 g_xTl[16L * 512 * 512];
__device__ __align__(16) bf16 g_r0h[4096 * 512];     // conv+pool+relu out hi/lo
__device__ __align__(16) bf16 g_r0l[4096 * 512];
__device__ __align__(16) bf16 g_rh[4096 * 512];      // after linear hi/lo
__device__ __align__(16) bf16 g_rl[4096 * 512];
__device__ float g_S[16L * 4096 * 512];              // logits fp32
__device__ __align__(16) bf16 g_Sh[16L * 4096 * 512];// softmax probs hi/lo
__device__ __align__(16) bf16 g_Sl[16L * 4096 * 512];

// ---------------- helpers ----------------
__device__ __forceinline__ uint32_t smem_u32(const void* p) {
    uint32_t a;
    asm("{ .reg .u64 t; cvta.to.shared.u64 t, %1; cvt.u32.u64 %0, t; }" : "=r"(a) : "l"(p));
    return a;
}
__device__ __forceinline__ void cpasync16(uint32_t dst, const void* src) {
    asm volatile("cp.async.cg.shared.global [%0], [%1], 16;" :: "r"(dst), "l"(src) : "memory");
}
#define CP_COMMIT() asm volatile("cp.async.commit_group;" ::: "memory")
#define CP_WAIT1()  asm volatile("cp.async.wait_group 1;" ::: "memory")
#define CP_WAIT0()  asm volatile("cp.async.wait_group 0;" ::: "memory")

__device__ __forceinline__ void ldsm4(uint32_t* r, uint32_t addr) {
    asm volatile("ldmatrix.sync.aligned.m8n8.x4.shared.b16 {%0,%1,%2,%3}, [%4];"
                 : "=r"(r[0]), "=r"(r[1]), "=r"(r[2]), "=r"(r[3]) : "r"(addr));
}
__device__ __forceinline__ void mma16816(float* c, const uint32_t* a, const uint32_t* b) {
    asm volatile("mma.sync.aligned.m16n8k16.row.col.f32.bf16.bf16.f32 "
        "{%0,%1,%2,%3}, {%4,%5,%6,%7}, {%8,%9}, {%0,%1,%2,%3};"
        : "+f"(c[0]), "+f"(c[1]), "+f"(c[2]), "+f"(c[3])
        : "r"(a[0]), "r"(a[1]), "r"(a[2]), "r"(a[3]), "r"(b[0]), "r"(b[1]));
}
__device__ __forceinline__ uint32_t swz(uint32_t off) { return off ^ ((off >> 3) & 0x70); }
__device__ __forceinline__ void split(float v, bf16* h, bf16* l) {
    bf16 hh = __float2bfloat16(v);
    *h = hh;
    *l = __float2bfloat16(v - __bfloat162float(hh));
}

// ---------------- GEMM: D(128x128) = A(128xK) . B(128xK)^T, 3-term bf16 split ----------
// 8 warps as 2(M) x 4(N); warp tile 64x32; K-step 32; 2-half ring inside 128B rows.
// Smem tiles (128 rows x 128B, SW128): Ah@0 Al@16K Bh@32K Bl@48K = 64KB.
// EPI 0: store fp32 C   EPI 1: +bias, split -> Eh/El   EPI 2: conv window+pool+relu
static constexpr int SMEMSZ = 128 * 132 * 4;           // 67584 (EPI2 buf >= 64KB operands)

template <int EPI>
__global__ void __launch_bounds__(256, 2)
mmagemm(const bf16* __restrict__ Ah, const bf16* __restrict__ Al,
        const bf16* __restrict__ Bh, const bf16* __restrict__ Bl,
        int K, long sA, long sB,
        float* __restrict__ C, long sC, int ldc,
        const float* __restrict__ bias,
        bf16* __restrict__ Eh, bf16* __restrict__ El)
{
    extern __shared__ char smem[];
    const uint32_t sb = smem_u32(smem);
    const int tid = threadIdx.x, wid = tid >> 5, lane = tid & 31;
    const int wm0 = (wid >> 2) * 64;       // warp row offset in tile
    const int wn0 = (wid & 3) * 32;        // warp col offset in tile
    const long z = blockIdx.z;
    const bf16* pA[2] = { Ah + z * sA, Al + z * sA };
    const bf16* pB[2] = { Bh + z * sB, Bl + z * sB };
    const long m0 = (long)blockIdx.y * 128;
    const int  n0 = blockIdx.x * 128;
    const int  KT = K >> 5;                // k32 steps

    float acc[4][4][4];
    #pragma unroll
    for (int mi = 0; mi < 4; mi++)
        #pragma unroll
        for (int ni = 0; ni < 4; ni++)
            #pragma unroll
            for (int r = 0; r < 4; r++)
                acc[mi][ni][r] = 0.f;

    // load one k32 block (32KB: 4 tiles x 128 rows x 64B) into half (kt2&1) of rows
    auto load_half = [&](int kt2) {
        const int h = (kt2 & 1) * 64;
        const int k0 = kt2 * 32;
        const bf16* srcs[4] = { pA[0] + m0 * K + k0, pA[1] + m0 * K + k0,
                                pB[0] + (long)n0 * K + k0, pB[1] + (long)n0 * K + k0 };
        #pragma unroll
        for (int t = 0; t < 4; t++) {
            uint32_t tb = sb + t * 16384;
            const bf16* sp = srcs[t];
            #pragma unroll
            for (int i = 0; i < 2; i++) {
                int c = tid + i * 256;              // 0..511
                int row = c >> 2, c16 = c & 3;
                cpasync16(tb + swz(row * 128 + h + c16 * 16), sp + (long)row * K + c16 * 8);
            }
        }
    };

    load_half(0); CP_COMMIT();
    load_half(1); CP_COMMIT();

    for (int kt = 0; kt < KT; kt++) {
        if (kt + 1 < KT) { CP_WAIT1(); } else { CP_WAIT0(); }
        __syncthreads();                            // data for kt ready, all warps here
        const uint32_t hoff = (kt & 1) * 64;

        #pragma unroll
        for (int kk = 0; kk < 2; kk++) {
            uint32_t a_h[4][4], a_l[4][4];
            #pragma unroll
            for (int mi = 0; mi < 4; mi++) {
                uint32_t off = (uint32_t)(wm0 + mi * 16 + (lane & 15)) * 128
                             + hoff + kk * 32 + (lane >> 4) * 16;
                ldsm4(a_h[mi], sb + swz(off));                 // Ah
                ldsm4(a_l[mi], sb + 16384 + swz(off));         // Al
            }
            #pragma unroll
            for (int q = 0; q < 2; q++) {
                uint32_t off = (uint32_t)(wn0 + q * 16 + (lane >> 4) * 8 + (lane & 7)) * 128
                             + hoff + kk * 32 + ((lane >> 3) & 1) * 16;
                uint32_t rh[4], rl[4];
                ldsm4(rh, sb + 32768 + swz(off));              // Bh
                ldsm4(rl, sb + 49152 + swz(off));              // Bl
                #pragma unroll
                for (int half = 0; half < 2; half++) {
                    int ni = 2 * q + half;
                    uint32_t bh[2] = { rh[2 * half], rh[2 * half + 1] };
                    uint32_t bl[2] = { rl[2 * half], rl[2 * half + 1] };
                    #pragma unroll
                    for (int mi = 0; mi < 4; mi++) {
                        mma16816(acc[mi][ni], a_h[mi], bh);
                        mma16816(acc[mi][ni], a_h[mi], bl);
                        mma16816(acc[mi][ni], a_l[mi], bh);
                    }
                }
            }
        }
        __syncthreads();                            // all reads of this half done
        if (kt + 2 < KT) { load_half(kt + 2); CP_COMMIT(); }
    }

    // -------- epilogue --------
    // acc (mi,ni,r): row = wm0+mi*16+(lane>>2)+(r>>1)*8, col = wn0+ni*8+(lane&3)*2+(r&1)
    if (EPI == 0) {
        #pragma unroll
        for (int mi = 0; mi < 4; mi++)
            #pragma unroll
            for (int ni = 0; ni < 4; ni++) {
                long row = m0 + wm0 + mi * 16 + (lane >> 2);
                int  col = n0 + wn0 + ni * 8 + (lane & 3) * 2;
                float* cp = C + z * sC + row * (long)ldc + col;
                *reinterpret_cast<float2*>(cp) =
                    make_float2(acc[mi][ni][0], acc[mi][ni][1]);
                *reinterpret_cast<float2*>(cp + 8L * ldc) =
                    make_float2(acc[mi][ni][2], acc[mi][ni][3]);
            }
    } else if (EPI == 1) {
        #pragma unroll
        for (int mi = 0; mi < 4; mi++)
            #pragma unroll
            for (int ni = 0; ni < 4; ni++) {
                long row = m0 + wm0 + mi * 16 + (lane >> 2);
                int  col = n0 + wn0 + ni * 8 + (lane & 3) * 2;
                #pragma unroll
                for (int r = 0; r < 4; r++) {
                    long rr = row + (r >> 1) * 8;
                    int  cc = col + (r & 1);
                    float v = acc[mi][ni][r] + bias[cc];
                    bf16 h, l; split(v, &h, &l);
                    Eh[rr * 512 + cc] = h;
                    El[rr * 512 + cc] = l;
                }
            }
    } else {
        // stage 128x128 fp32 tile into smem (pitch 132), then window-sum/pool/relu
        float* buf = reinterpret_cast<float*>(smem);
        #pragma unroll
        for (int mi = 0; mi < 4; mi++)
            #pragma unroll
            for (int ni = 0; ni < 4; ni++) {
                int row = wm0 + mi * 16 + (lane >> 2);
                int col = wn0 + ni * 8 + (lane & 3) * 2;
                *reinterpret_cast<float2*>(buf + row * 132 + col) =
                    make_float2(acc[mi][ni][0], acc[mi][ni][1]);
                *reinterpret_cast<float2*>(buf + (row + 8) * 132 + col) =
                    make_float2(acc[mi][ni][2], acc[mi][ni][3]);
            }
        __syncthreads();
        if (tid < 128) {
            int lab = tid >> 5, f = tid & 31;       // 4 labels x 32 filters
            const float* g = buf + (lab * 32) * 132 + f * 4;
            float P1 = 0.f, P2 = 0.f, P3 = 0.f, best = -FLT_MAX;
            #pragma unroll
            for (int s = 0; s < 32; s++) {
                float4 q = *reinterpret_cast<const float4*>(g + s * 132);
                if (s >= 3) best = fmaxf(best, P3 + q.w);   // completes window t = s-3
                P3 = P2 + q.z;
                P2 = P1 + q.y;
                P1 = q.x;
            }
            int  fg    = (n0 >> 2) + f;                     // global filter
            long lab_g = (m0 >> 5) + lab;                   // global label
            float v = fmaxf(best + bias[fg], 0.f);
            bf16 h, l; split(v, &h, &l);
            Eh[lab_g * 512 + fg] = h;
            El[lab_g * 512 + fg] = l;
        }
    }
}

// ---------------- prep kernels ----------------
__global__ void k_prep_A(const float* __restrict__ reps) {
    long row = blockIdx.x; int k = threadIdx.x;          // 320 threads
    float v = (k < 300) ? reps[row * 300 + k] : 0.f;
    bf16 h, l; split(v, &h, &l);
    g_Ah[row * 320 + k] = h;
    g_Al[row * 320 + k] = l;
}
__global__ void k_prep_B(const float* __restrict__ cw) {
    int c = blockIdx.x, e = threadIdx.x;                 // 2048 x 320
    int f = c >> 2, k = c & 3;
    float v = (e < 300) ? cw[f * 1200 + e * 4 + k] : 0.f;
    bf16 h, l; split(v, &h, &l);
    g_Bh[c * 320 + e] = h;
    g_Bl[c * 320 + e] = l;
}
__global__ void k_prep_lin(const float* __restrict__ lw) {
    int i = blockIdx.x * 512 + threadIdx.x;              // 512 x 512
    bf16 h, l; split(lw[i], &h, &l);
    g_lnh[i] = h;  g_lnl[i] = l;
}
// merged: direct split (xh/xl) + transposed split (xTh/xTl), one read of x
__global__ void k_prep_x(const float* __restrict__ x) {
    __shared__ float t[32][33];
    int b = blockIdx.z, l0 = blockIdx.x * 32, f0 = blockIdx.y * 32;
    int tx = threadIdx.x, ty = threadIdx.y;              // (32, 8)
    long base = (long)b * 262144;
    #pragma unroll
    for (int j = 0; j < 4; j++) {
        long o = base + (long)(l0 + ty + 8 * j) * 512 + f0 + tx;
        float v = x[o];
        t[ty + 8 * j][tx] = v;
        bf16 h, l; split(v, &h, &l);
        g_xh[o] = h;  g_xl[o] = l;
    }
    __syncthreads();
    #pragma unroll
    for (int j = 0; j < 4; j++) {
        float v = t[tx][ty + 8 * j];                     // = x[b][l0+tx][f0+ty+8j]
        bf16 h, l; split(v, &h, &l);
        long o = base + (long)(f0 + ty + 8 * j) * 512 + l0 + tx;
        g_xTh[o] = h;  g_xTl[o] = l;
    }
}
// ---------------- softmax over L=512, warp per row, emits hi/lo probs ----------------
__global__ void k_softmax(const float* __restrict__ S) {
    long row = (long)blockIdx.x * 8 + (threadIdx.x >> 5);
    int lane = threadIdx.x & 31;
    const float* p = S + row * 512;
    float v[16], m = -FLT_MAX;
    #pragma unroll
    for (int i = 0; i < 16; i++) { v[i] = p[lane + 32 * i]; m = fmaxf(m, v[i]); }
    #pragma unroll
    for (int o = 16; o > 0; o >>= 1) m = fmaxf(m, __shfl_xor_sync(0xffffffffu, m, o));
    float s = 0.f;
    #pragma unroll
    for (int i = 0; i < 16; i++) { v[i] = expf(v[i] - m); s += v[i]; }
    #pragma unroll
    for (int o = 16; o > 0; o >>= 1) s += __shfl_xor_sync(0xffffffffu, s, o);
    float inv = 1.f / s;
    #pragma unroll
    for (int i = 0; i < 16; i++) {
        float q = v[i] * inv;
        bf16 h, l; split(q, &h, &l);
        g_Sh[row * 512 + lane + 32 * i] = h;
        g_Sl[row * 512 + lane + 32 * i] = l;
    }
}

// ---------------- launch ----------------
extern "C" void kernel_launch(void* const* d_in, const int* in_sizes, int n_in,
                              void* d_out, int out_size)
{
    const float* x      = (const float*)d_in[0];
    const float* reps   = (const float*)d_in[1];
    const float* conv_w = (const float*)d_in[2];
    const float* conv_b = (const float*)d_in[3];
    const float* lin_w  = (const float*)d_in[4];
    const float* lin_b  = (const float*)d_in[5];
    float* out = (float*)d_out;

    cudaFuncSetAttribute(mmagemm<0>, cudaFuncAttributeMaxDynamicSharedMemorySize, SMEMSZ);
    cudaFuncSetAttribute(mmagemm<1>, cudaFuncAttributeMaxDynamicSharedMemorySize, SMEMSZ);
    cudaFuncSetAttribute(mmagemm<2>, cudaFuncAttributeMaxDynamicSharedMemorySize, SMEMSZ);

    bf16 *Ah, *Al, *Bh, *Bl, *lnh, *lnl, *xh, *xl, *xTh, *xTl, *r0h, *r0l, *rh, *rl, *Sh, *Sl;
    float* S;
    cudaGetSymbolAddress((void**)&Ah, g_Ah);   cudaGetSymbolAddress((void**)&Al, g_Al);
    cudaGetSymbolAddress((void**)&Bh, g_Bh);   cudaGetSymbolAddress((void**)&Bl, g_Bl);
    cudaGetSymbolAddress((void**)&lnh, g_lnh); cudaGetSymbolAddress((void**)&lnl, g_lnl);
    cudaGetSymbolAddress((void**)&xh, g_xh);   cudaGetSymbolAddress((void**)&xl, g_xl);
    cudaGetSymbolAddress((void**)&xTh, g_xTh); cudaGetSymbolAddress((void**)&xTl, g_xTl);
    cudaGetSymbolAddress((void**)&r0h, g_r0h); cudaGetSymbolAddress((void**)&r0l, g_r0l);
    cudaGetSymbolAddress((void**)&rh, g_rh);   cudaGetSymbolAddress((void**)&rl, g_rl);
    cudaGetSymbolAddress((void**)&Sh, g_Sh);   cudaGetSymbolAddress((void**)&Sl, g_Sl);
    cudaGetSymbolAddress((void**)&S, g_S);

    // operand prep
    k_prep_A<<<131072, 320>>>(reps);
    k_prep_B<<<2048, 320>>>(conv_w);
    k_prep_lin<<<512, 512>>>(lin_w);
    k_prep_x<<<dim3(16, 16, 16), dim3(32, 8)>>>(x);

    // conv GEMM (131072 x 2048, K=320) with fused window+pool+relu epilogue -> r0
    mmagemm<2><<<dim3(16, 1024, 1), 256, SMEMSZ>>>(
        Ah, Al, Bh, Bl, 320, 0, 0, nullptr, 0, 0, conv_b, r0h, r0l);

    // linear (4096 x 512, K=512) + bias -> r (split)
    mmagemm<1><<<dim3(4, 32, 1), 256, SMEMSZ>>>(
        r0h, r0l, lnh, lnl, 512, 0, 0, nullptr, 0, 0, lin_b, rh, rl);

    // logits per batch: S[b] = r @ x[b]^T  (4096 x 512)
    mmagemm<0><<<dim3(4, 32, 16), 256, SMEMSZ>>>(
        rh, rl, xh, xl, 512, 0, 262144, S, 2097152, 512, nullptr, nullptr, nullptr);

    // softmax -> probs (split)
    k_softmax<<<(16 * 4096) / 8, 256>>>(S);

    // out[b] = P[b] @ x[b]  (4096 x 512)
    mmagemm<0><<<dim3(4, 32, 16), 256, SMEMSZ>>>(
        Sh, Sl, xTh, xTl, 512, 2097152, 262144, out, 2097152, 512, nullptr, nullptr, nullptr);
}

// round 15
// speedup vs baseline: 4.2091x; 1.1383x over previous
#include <cuda_runtime.h>
#include <cuda_bf16.h>
#include <math.h>
#include <cfloat>
#include <cstdint>

typedef __nv_bfloat16 bf16;

// ============================================================================
// x(16,512,512) reps(4096,32,300) conv_w(512,300,4) conv_b(512)
// lin_w(512,512) lin_b(512) -> out(16,4096,512) fp32
// GEMMs via mma.sync.m16n8k16 bf16, 3-term split: hi*hi + hi*lo + lo*hi.
// Final P@x replaced by fused softmax + thresholded sparse weighted sum
// (softmax is near-argmax: logit sigma ~72 -> tail probabilities ~e^-20).
// ============================================================================

// ---------------- static scratch ----------------
__device__ __align__(16) bf16 g_Ah[131072L * 320];   // conv A hi (K padded 300->320)
__device__ __align__(16) bf16 g_Al[131072L * 320];   // conv A lo
__device__ __align__(16) bf16 g_Bh[2048 * 320];      // conv B: [c=f*4+k][e]
__device__ __align__(16) bf16 g_Bl[2048 * 320];
__device__ __align__(16) bf16 g_lnh[512 * 512];      // lin_w [f][c] (native = B layout)
__device__ __align__(16) bf16 g_lnl[512 * 512];
__device__ __align__(16) bf16 g_xh[16L * 512 * 512]; // x elementwise (B of logits)
__device__ __align__(16) bf16 g_xl[16L * 512 * 512];
__device__ __align__(16) bf16 g_r0h[4096 * 512];     // conv+pool+relu out hi/lo
__device__ __align__(16) bf16 g_r0l[4096 * 512];
__device__ __align__(16) bf16 g_rh[4096 * 512];      // after linear hi/lo
__device__ __align__(16) bf16 g_rl[4096 * 512];
__device__ float g_S[16L * 4096 * 512];              // logits fp32

// ---------------- helpers ----------------
__device__ __forceinline__ uint32_t smem_u32(const void* p) {
    uint32_t a;
    asm("{ .reg .u64 t; cvta.to.shared.u64 t, %1; cvt.u32.u64 %0, t; }" : "=r"(a) : "l"(p));
    return a;
}
__device__ __forceinline__ void cpasync16(uint32_t dst, const void* src) {
    asm volatile("cp.async.cg.shared.global [%0], [%1], 16;" :: "r"(dst), "l"(src) : "memory");
}
#define CP_COMMIT() asm volatile("cp.async.commit_group;" ::: "memory")
#define CP_WAIT1()  asm volatile("cp.async.wait_group 1;" ::: "memory")
#define CP_WAIT0()  asm volatile("cp.async.wait_group 0;" ::: "memory")

__device__ __forceinline__ void ldsm4(uint32_t* r, uint32_t addr) {
    asm volatile("ldmatrix.sync.aligned.m8n8.x4.shared.b16 {%0,%1,%2,%3}, [%4];"
                 : "=r"(r[0]), "=r"(r[1]), "=r"(r[2]), "=r"(r[3]) : "r"(addr));
}
__device__ __forceinline__ void mma16816(float* c, const uint32_t* a, const uint32_t* b) {
    asm volatile("mma.sync.aligned.m16n8k16.row.col.f32.bf16.bf16.f32 "
        "{%0,%1,%2,%3}, {%4,%5,%6,%7}, {%8,%9}, {%0,%1,%2,%3};"
        : "+f"(c[0]), "+f"(c[1]), "+f"(c[2]), "+f"(c[3])
        : "r"(a[0]), "r"(a[1]), "r"(a[2]), "r"(a[3]), "r"(b[0]), "r"(b[1]));
}
__device__ __forceinline__ uint32_t swz(uint32_t off) { return off ^ ((off >> 3) & 0x70); }
__device__ __forceinline__ void split(float v, bf16* h, bf16* l) {
    bf16 hh = __float2bfloat16(v);
    *h = hh;
    *l = __float2bfloat16(v - __bfloat162float(hh));
}

// ---------------- GEMM: D(128x128) = A(128xK) . B(128xK)^T, 3-term bf16 split ----------
// 8 warps as 2(M) x 4(N); warp tile 64x32; K-step 32; 2-half ring inside 128B rows.
// Smem tiles (128 rows x 128B, SW128): Ah@0 Al@16K Bh@32K Bl@48K = 64KB.
// EPI 0: store fp32 C   EPI 1: +bias, split -> Eh/El   EPI 2: conv window+pool+relu
static constexpr int SMEMSZ = 128 * 132 * 4;           // 67584 (EPI2 buf >= 64KB operands)

template <int EPI>
__global__ void __launch_bounds__(256, 2)
mmagemm(const bf16* __restrict__ Ah, const bf16* __restrict__ Al,
        const bf16* __restrict__ Bh, const bf16* __restrict__ Bl,
        int K, long sA, long sB,
        float* __restrict__ C, long sC, int ldc,
        const float* __restrict__ bias,
        bf16* __restrict__ Eh, bf16* __restrict__ El)
{
    extern __shared__ char smem[];
    const uint32_t sb = smem_u32(smem);
    const int tid = threadIdx.x, wid = tid >> 5, lane = tid & 31;
    const int wm0 = (wid >> 2) * 64;       // warp row offset in tile
    const int wn0 = (wid & 3) * 32;        // warp col offset in tile
    const long z = blockIdx.z;
    const bf16* pA[2] = { Ah + z * sA, Al + z * sA };
    const bf16* pB[2] = { Bh + z * sB, Bl + z * sB };
    const long m0 = (long)blockIdx.y * 128;
    const int  n0 = blockIdx.x * 128;
    const int  KT = K >> 5;                // k32 steps

    float acc[4][4][4];
    #pragma unroll
    for (int mi = 0; mi < 4; mi++)
        #pragma unroll
        for (int ni = 0; ni < 4; ni++)
            #pragma unroll
            for (int r = 0; r < 4; r++)
                acc[mi][ni][r] = 0.f;

    // load one k32 block (32KB: 4 tiles x 128 rows x 64B) into half (kt2&1) of rows
    auto load_half = [&](int kt2) {
        const int h = (kt2 & 1) * 64;
        const int k0 = kt2 * 32;
        const bf16* srcs[4] = { pA[0] + m0 * K + k0, pA[1] + m0 * K + k0,
                                pB[0] + (long)n0 * K + k0, pB[1] + (long)n0 * K + k0 };
        #pragma unroll
        for (int t = 0; t < 4; t++) {
            uint32_t tb = sb + t * 16384;
            const bf16* sp = srcs[t];
            #pragma unroll
            for (int i = 0; i < 2; i++) {
                int c = tid + i * 256;              // 0..511
                int row = c >> 2, c16 = c & 3;
                cpasync16(tb + swz(row * 128 + h + c16 * 16), sp + (long)row * K + c16 * 8);
            }
        }
    };

    load_half(0); CP_COMMIT();
    load_half(1); CP_COMMIT();

    for (int kt = 0; kt < KT; kt++) {
        if (kt + 1 < KT) { CP_WAIT1(); } else { CP_WAIT0(); }
        __syncthreads();                            // data for kt ready, all warps here
        const uint32_t hoff = (kt & 1) * 64;

        #pragma unroll
        for (int kk = 0; kk < 2; kk++) {
            uint32_t a_h[4][4], a_l[4][4];
            #pragma unroll
            for (int mi = 0; mi < 4; mi++) {
                uint32_t off = (uint32_t)(wm0 + mi * 16 + (lane & 15)) * 128
                             + hoff + kk * 32 + (lane >> 4) * 16;
                ldsm4(a_h[mi], sb + swz(off));                 // Ah
                ldsm4(a_l[mi], sb + 16384 + swz(off));         // Al
            }
            #pragma unroll
            for (int q = 0; q < 2; q++) {
                uint32_t off = (uint32_t)(wn0 + q * 16 + (lane >> 4) * 8 + (lane & 7)) * 128
                             + hoff + kk * 32 + ((lane >> 3) & 1) * 16;
                uint32_t rh[4], rl[4];
                ldsm4(rh, sb + 32768 + swz(off));              // Bh
                ldsm4(rl, sb + 49152 + swz(off));              // Bl
                #pragma unroll
                for (int half = 0; half < 2; half++) {
                    int ni = 2 * q + half;
                    uint32_t bh[2] = { rh[2 * half], rh[2 * half + 1] };
                    uint32_t bl[2] = { rl[2 * half], rl[2 * half + 1] };
                    #pragma unroll
                    for (int mi = 0; mi < 4; mi++) {
                        mma16816(acc[mi][ni], a_h[mi], bh);
                        mma16816(acc[mi][ni], a_h[mi], bl);
                        mma16816(acc[mi][ni], a_l[mi], bh);
                    }
                }
            }
        }
        __syncthreads();                            // all reads of this half done
        if (kt + 2 < KT) { load_half(kt + 2); CP_COMMIT(); }
    }

    // -------- epilogue --------
    // acc (mi,ni,r): row = wm0+mi*16+(lane>>2)+(r>>1)*8, col = wn0+ni*8+(lane&3)*2+(r&1)
    if (EPI == 0) {
        #pragma unroll
        for (int mi = 0; mi < 4; mi++)
            #pragma unroll
            for (int ni = 0; ni < 4; ni++) {
                long row = m0 + wm0 + mi * 16 + (lane >> 2);
                int  col = n0 + wn0 + ni * 8 + (lane & 3) * 2;
                float* cp = C + z * sC + row * (long)ldc + col;
                *reinterpret_cast<float2*>(cp) =
                    make_float2(acc[mi][ni][0], acc[mi][ni][1]);
                *reinterpret_cast<float2*>(cp + 8L * ldc) =
                    make_float2(acc[mi][ni][2], acc[mi][ni][3]);
            }
    } else if (EPI == 1) {
        #pragma unroll
        for (int mi = 0; mi < 4; mi++)
            #pragma unroll
            for (int ni = 0; ni < 4; ni++) {
                long row = m0 + wm0 + mi * 16 + (lane >> 2);
                int  col = n0 + wn0 + ni * 8 + (lane & 3) * 2;
                #pragma unroll
                for (int r = 0; r < 4; r++) {
                    long rr = row + (r >> 1) * 8;
                    int  cc = col + (r & 1);
                    float v = acc[mi][ni][r] + bias[cc];
                    bf16 h, l; split(v, &h, &l);
                    Eh[rr * 512 + cc] = h;
                    El[rr * 512 + cc] = l;
                }
            }
    } else {
        // stage 128x128 fp32 tile into smem (pitch 132), then window-sum/pool/relu
        float* buf = reinterpret_cast<float*>(smem);
        #pragma unroll
        for (int mi = 0; mi < 4; mi++)
            #pragma unroll
            for (int ni = 0; ni < 4; ni++) {
                int row = wm0 + mi * 16 + (lane >> 2);
                int col = wn0 + ni * 8 + (lane & 3) * 2;
                *reinterpret_cast<float2*>(buf + row * 132 + col) =
                    make_float2(acc[mi][ni][0], acc[mi][ni][1]);
                *reinterpret_cast<float2*>(buf + (row + 8) * 132 + col) =
                    make_float2(acc[mi][ni][2], acc[mi][ni][3]);
            }
        __syncthreads();
        if (tid < 128) {
            int lab = tid >> 5, f = tid & 31;       // 4 labels x 32 filters
            const float* g = buf + (lab * 32) * 132 + f * 4;
            float P1 = 0.f, P2 = 0.f, P3 = 0.f, best = -FLT_MAX;
            #pragma unroll
            for (int s = 0; s < 32; s++) {
                float4 q = *reinterpret_cast<const float4*>(g + s * 132);
                if (s >= 3) best = fmaxf(best, P3 + q.w);   // completes window t = s-3
                P3 = P2 + q.z;
                P2 = P1 + q.y;
                P1 = q.x;
            }
            int  fg    = (n0 >> 2) + f;                     // global filter
            long lab_g = (m0 >> 5) + lab;                   // global label
            float v = fmaxf(best + bias[fg], 0.f);
            bf16 h, l; split(v, &h, &l);
            Eh[lab_g * 512 + fg] = h;
            El[lab_g * 512 + fg] = l;
        }
    }
}

// ---------------- prep kernels ----------------
__global__ void k_prep_A(const float* __restrict__ reps) {
    long row = blockIdx.x; int k = threadIdx.x;          // 320 threads
    float v = (k < 300) ? reps[row * 300 + k] : 0.f;
    bf16 h, l; split(v, &h, &l);
    g_Ah[row * 320 + k] = h;
    g_Al[row * 320 + k] = l;
}
__global__ void k_prep_B(const float* __restrict__ cw) {
    int c = blockIdx.x, e = threadIdx.x;                 // 2048 x 320
    int f = c >> 2, k = c & 3;
    float v = (e < 300) ? cw[f * 1200 + e * 4 + k] : 0.f;
    bf16 h, l; split(v, &h, &l);
    g_Bh[c * 320 + e] = h;
    g_Bl[c * 320 + e] = l;
}
__global__ void k_prep_lin(const float* __restrict__ lw) {
    int i = blockIdx.x * 512 + threadIdx.x;              // 512 x 512
    bf16 h, l; split(lw[i], &h, &l);
    g_lnh[i] = h;  g_lnl[i] = l;
}
__global__ void k_prep_x(const float* __restrict__ x) {
    long i = (long)blockIdx.x * 256 + threadIdx.x;       // 16*512*512
    bf16 h, l; split(x[i], &h, &l);
    g_xh[i] = h;  g_xl[i] = l;
}

// ---------------- fused softmax + sparse P@x ----------------
// One warp per (b,n) row. Exact softmax denominator over all 512 logits;
// only survivors with p > 1e-7 contribute to out[b,n,:] = sum_l p_l * x[b,l,:].
// Logit sigma ~72 -> typically 1-3 survivors; truncation error <= 512*1e-7.
__global__ void __launch_bounds__(256)
k_softmax_spmm(const float* __restrict__ S, const float* __restrict__ x,
               float* __restrict__ out)
{
    const long row  = (long)blockIdx.x * 8 + (threadIdx.x >> 5);  // 0..65535
    const int  lane = threadIdx.x & 31;
    const float* p  = S + row * 512;
    const float* xb = x + (row >> 12) * 262144;          // x[b]

    float v[16], m = -FLT_MAX;
    #pragma unroll
    for (int i = 0; i < 16; i++) { v[i] = p[lane + 32 * i]; m = fmaxf(m, v[i]); }
    #pragma unroll
    for (int o = 16; o > 0; o >>= 1) m = fmaxf(m, __shfl_xor_sync(0xffffffffu, m, o));

    float s = 0.f;
    #pragma unroll
    for (int i = 0; i < 16; i++) { v[i] = expf(v[i] - m); s += v[i]; }
    #pragma unroll
    for (int o = 16; o > 0; o >>= 1) s += __shfl_xor_sync(0xffffffffu, s, o);

    const float thr = s * 1e-7f;
    float acc[16];
    #pragma unroll
    for (int c = 0; c < 16; c++) acc[c] = 0.f;

    #pragma unroll
    for (int j = 0; j < 16; j++) {
        unsigned mask = __ballot_sync(0xffffffffu, v[j] > thr);
        while (mask) {
            int src = __ffs(mask) - 1;
            mask &= mask - 1;
            float pv = __shfl_sync(0xffffffffu, v[j], src);
            const float* xr = xb + (long)(src + 32 * j) * 512;
            #pragma unroll
            for (int c = 0; c < 16; c++)
                acc[c] = fmaf(pv, xr[lane + 32 * c], acc[c]);
        }
    }
    const float inv = 1.f / s;
    float* op = out + row * 512;
    #pragma unroll
    for (int c = 0; c < 16; c++) op[lane + 32 * c] = acc[c] * inv;
}

// ---------------- launch ----------------
extern "C" void kernel_launch(void* const* d_in, const int* in_sizes, int n_in,
                              void* d_out, int out_size)
{
    const float* x      = (const float*)d_in[0];
    const float* reps   = (const float*)d_in[1];
    const float* conv_w = (const float*)d_in[2];
    const float* conv_b = (const float*)d_in[3];
    const float* lin_w  = (const float*)d_in[4];
    const float* lin_b  = (const float*)d_in[5];
    float* out = (float*)d_out;

    cudaFuncSetAttribute(mmagemm<0>, cudaFuncAttributeMaxDynamicSharedMemorySize, SMEMSZ);
    cudaFuncSetAttribute(mmagemm<1>, cudaFuncAttributeMaxDynamicSharedMemorySize, SMEMSZ);
    cudaFuncSetAttribute(mmagemm<2>, cudaFuncAttributeMaxDynamicSharedMemorySize, SMEMSZ);

    bf16 *Ah, *Al, *Bh, *Bl, *lnh, *lnl, *xh, *xl, *r0h, *r0l, *rh, *rl;
    float* S;
    cudaGetSymbolAddress((void**)&Ah, g_Ah);   cudaGetSymbolAddress((void**)&Al, g_Al);
    cudaGetSymbolAddress((void**)&Bh, g_Bh);   cudaGetSymbolAddress((void**)&Bl, g_Bl);
    cudaGetSymbolAddress((void**)&lnh, g_lnh); cudaGetSymbolAddress((void**)&lnl, g_lnl);
    cudaGetSymbolAddress((void**)&xh, g_xh);   cudaGetSymbolAddress((void**)&xl, g_xl);
    cudaGetSymbolAddress((void**)&r0h, g_r0h); cudaGetSymbolAddress((void**)&r0l, g_r0l);
    cudaGetSymbolAddress((void**)&rh, g_rh);   cudaGetSymbolAddress((void**)&rl, g_rl);
    cudaGetSymbolAddress((void**)&S, g_S);

    // operand prep
    k_prep_A<<<131072, 320>>>(reps);
    k_prep_B<<<2048, 320>>>(conv_w);
    k_prep_lin<<<512, 512>>>(lin_w);
    k_prep_x<<<(16 * 512 * 512) / 256, 256>>>(x);

    // conv GEMM (131072 x 2048, K=320) with fused window+pool+relu epilogue -> r0
    mmagemm<2><<<dim3(16, 1024, 1), 256, SMEMSZ>>>(
        Ah, Al, Bh, Bl, 320, 0, 0, nullptr, 0, 0, conv_b, r0h, r0l);

    // linear (4096 x 512, K=512) + bias -> r (split)
    mmagemm<1><<<dim3(4, 32, 1), 256, SMEMSZ>>>(
        r0h, r0l, lnh, lnl, 512, 0, 0, nullptr, 0, 0, lin_b, rh, rl);

    // logits per batch: S[b] = r @ x[b]^T  (4096 x 512)
    mmagemm<0><<<dim3(4, 32, 16), 256, SMEMSZ>>>(
        rh, rl, xh, xl, 512, 0, 262144, S, 2097152, 512, nullptr, nullptr, nullptr);

    // fused softmax + sparse P@x -> out
    k_softmax_spmm<<<(16 * 4096) / 8, 256>>>(S, x, out);
}

// round 16
// speedup vs baseline: 4.3862x; 1.0421x over previous
#include <cuda_runtime.h>
#include <cuda_bf16.h>
#include <math.h>
#include <cfloat>
#include <cstdint>

typedef __nv_bfloat16 bf16;

// ============================================================================
// x(16,512,512) reps(4096,32,300) conv_w(512,300,4) conv_b(512)
// lin_w(512,512) lin_b(512) -> out(16,4096,512) fp32
// GEMMs via mma.sync.m16n8k16 bf16, 3-term split: hi*hi + hi*lo + lo*hi.
// Final P@x = fused softmax + thresholded sparse weighted sum.
// Conv K padded to 304 (memory stride 320); last ring step runs k16 only.
// All prep kernels use packed bf16x2 stores.
// ============================================================================

// ---------------- static scratch ----------------
__device__ __align__(16) bf16 g_Ah[131072L * 320];   // conv A hi (stride 320, Kc=304)
__device__ __align__(16) bf16 g_Al[131072L * 320];   // conv A lo
__device__ __align__(16) bf16 g_Bh[2048 * 320];      // conv B: [c=f*4+k][e]
__device__ __align__(16) bf16 g_Bl[2048 * 320];
__device__ __align__(16) bf16 g_lnh[512 * 512];      // lin_w [f][c] (native = B layout)
__device__ __align__(16) bf16 g_lnl[512 * 512];
__device__ __align__(16) bf16 g_xh[16L * 512 * 512]; // x elementwise (B of logits)
__device__ __align__(16) bf16 g_xl[16L * 512 * 512];
__device__ __align__(16) bf16 g_r0h[4096 * 512];     // conv+pool+relu out hi/lo
__device__ __align__(16) bf16 g_r0l[4096 * 512];
__device__ __align__(16) bf16 g_rh[4096 * 512];      // after linear hi/lo
__device__ __align__(16) bf16 g_rl[4096 * 512];
__device__ float g_S[16L * 4096 * 512];              // logits fp32

// ---------------- helpers ----------------
__device__ __forceinline__ uint32_t smem_u32(const void* p) {
    uint32_t a;
    asm("{ .reg .u64 t; cvta.to.shared.u64 t, %1; cvt.u32.u64 %0, t; }" : "=r"(a) : "l"(p));
    return a;
}
__device__ __forceinline__ void cpasync16(uint32_t dst, const void* src) {
    asm volatile("cp.async.cg.shared.global [%0], [%1], 16;" :: "r"(dst), "l"(src) : "memory");
}
#define CP_COMMIT() asm volatile("cp.async.commit_group;" ::: "memory")
#define CP_WAIT1()  asm volatile("cp.async.wait_group 1;" ::: "memory")
#define CP_WAIT0()  asm volatile("cp.async.wait_group 0;" ::: "memory")

__device__ __forceinline__ void ldsm4(uint32_t* r, uint32_t addr) {
    asm volatile("ldmatrix.sync.aligned.m8n8.x4.shared.b16 {%0,%1,%2,%3}, [%4];"
                 : "=r"(r[0]), "=r"(r[1]), "=r"(r[2]), "=r"(r[3]) : "r"(addr));
}
__device__ __forceinline__ void mma16816(float* c, const uint32_t* a, const uint32_t* b) {
    asm volatile("mma.sync.aligned.m16n8k16.row.col.f32.bf16.bf16.f32 "
        "{%0,%1,%2,%3}, {%4,%5,%6,%7}, {%8,%9}, {%0,%1,%2,%3};"
        : "+f"(c[0]), "+f"(c[1]), "+f"(c[2]), "+f"(c[3])
        : "r"(a[0]), "r"(a[1]), "r"(a[2]), "r"(a[3]), "r"(b[0]), "r"(b[1]));
}
__device__ __forceinline__ uint32_t swz(uint32_t off) { return off ^ ((off >> 3) & 0x70); }
__device__ __forceinline__ void split(float v, bf16* h, bf16* l) {
    bf16 hh = __float2bfloat16(v);
    *h = hh;
    *l = __float2bfloat16(v - __bfloat162float(hh));
}
// split two floats, return packed bf16x2 words (element 0 in low 16 bits)
__device__ __forceinline__ void split2(float a, float b, uint32_t* hp, uint32_t* lp) {
    bf16 h0, l0, h1, l1;
    split(a, &h0, &l0);
    split(b, &h1, &l1);
    *hp = (uint32_t)__bfloat16_as_ushort(h0) | ((uint32_t)__bfloat16_as_ushort(h1) << 16);
    *lp = (uint32_t)__bfloat16_as_ushort(l0) | ((uint32_t)__bfloat16_as_ushort(l1) << 16);
}

// ---------------- GEMM: D(128x128) = A(128xKc) . B(128xKc)^T, 3-term bf16 split --------
// 8 warps as 2(M) x 4(N); warp tile 64x32; K-step 32; 2-half ring inside 128B rows.
// K = memory stride (elements), Kc = compute K (multiple of 16; Kc <= K).
// Smem tiles (128 rows x 128B, SW128): Ah@0 Al@16K Bh@32K Bl@48K = 64KB.
// EPI 0: store fp32 C   EPI 1: +bias, split -> Eh/El   EPI 2: conv window+pool+relu
static constexpr int SMEMSZ = 128 * 132 * 4;           // 67584 (EPI2 buf >= 64KB operands)

template <int EPI>
__global__ void __launch_bounds__(256, 2)
mmagemm(const bf16* __restrict__ Ah, const bf16* __restrict__ Al,
        const bf16* __restrict__ Bh, const bf16* __restrict__ Bl,
        int K, int Kc, long sA, long sB,
        float* __restrict__ C, long sC, int ldc,
        const float* __restrict__ bias,
        bf16* __restrict__ Eh, bf16* __restrict__ El)
{
    extern __shared__ char smem[];
    const uint32_t sb = smem_u32(smem);
    const int tid = threadIdx.x, wid = tid >> 5, lane = tid & 31;
    const int wm0 = (wid >> 2) * 64;       // warp row offset in tile
    const int wn0 = (wid & 3) * 32;        // warp col offset in tile
    const long z = blockIdx.z;
    const bf16* pA[2] = { Ah + z * sA, Al + z * sA };
    const bf16* pB[2] = { Bh + z * sB, Bl + z * sB };
    const long m0 = (long)blockIdx.y * 128;
    const int  n0 = blockIdx.x * 128;
    const int  KT = (Kc + 31) >> 5;        // k32 steps (last may be half)
    const int  lastkk = ((Kc & 31) == 16) ? 1 : 2;

    float acc[4][4][4];
    #pragma unroll
    for (int mi = 0; mi < 4; mi++)
        #pragma unroll
        for (int ni = 0; ni < 4; ni++)
            #pragma unroll
            for (int r = 0; r < 4; r++)
                acc[mi][ni][r] = 0.f;

    // load one k32 block (32KB: 4 tiles x 128 rows x 64B) into half (kt2&1) of rows
    auto load_half = [&](int kt2) {
        const int h = (kt2 & 1) * 64;
        const int k0 = kt2 * 32;
        const bf16* srcs[4] = { pA[0] + m0 * K + k0, pA[1] + m0 * K + k0,
                                pB[0] + (long)n0 * K + k0, pB[1] + (long)n0 * K + k0 };
        #pragma unroll
        for (int t = 0; t < 4; t++) {
            uint32_t tb = sb + t * 16384;
            const bf16* sp = srcs[t];
            #pragma unroll
            for (int i = 0; i < 2; i++) {
                int c = tid + i * 256;              // 0..511
                int row = c >> 2, c16 = c & 3;
                cpasync16(tb + swz(row * 128 + h + c16 * 16), sp + (long)row * K + c16 * 8);
            }
        }
    };

    load_half(0); CP_COMMIT();
    load_half(1); CP_COMMIT();

    for (int kt = 0; kt < KT; kt++) {
        if (kt + 1 < KT) { CP_WAIT1(); } else { CP_WAIT0(); }
        __syncthreads();                            // data for kt ready, all warps here
        const uint32_t hoff = (kt & 1) * 64;
        const int kkmax = (kt == KT - 1) ? lastkk : 2;

        for (int kk = 0; kk < kkmax; kk++) {
            uint32_t a_h[4][4], a_l[4][4];
            #pragma unroll
            for (int mi = 0; mi < 4; mi++) {
                uint32_t off = (uint32_t)(wm0 + mi * 16 + (lane & 15)) * 128
                             + hoff + kk * 32 + (lane >> 4) * 16;
                ldsm4(a_h[mi], sb + swz(off));                 // Ah
                ldsm4(a_l[mi], sb + 16384 + swz(off));         // Al
            }
            #pragma unroll
            for (int q = 0; q < 2; q++) {
                uint32_t off = (uint32_t)(wn0 + q * 16 + (lane >> 4) * 8 + (lane & 7)) * 128
                             + hoff + kk * 32 + ((lane >> 3) & 1) * 16;
                uint32_t rh[4], rl[4];
                ldsm4(rh, sb + 32768 + swz(off));              // Bh
                ldsm4(rl, sb + 49152 + swz(off));              // Bl
                #pragma unroll
                for (int half = 0; half < 2; half++) {
                    int ni = 2 * q + half;
                    uint32_t bh[2] = { rh[2 * half], rh[2 * half + 1] };
                    uint32_t bl[2] = { rl[2 * half], rl[2 * half + 1] };
                    #pragma unroll
                    for (int mi = 0; mi < 4; mi++) {
                        mma16816(acc[mi][ni], a_h[mi], bh);
                        mma16816(acc[mi][ni], a_h[mi], bl);
                        mma16816(acc[mi][ni], a_l[mi], bh);
                    }
                }
            }
        }
        __syncthreads();                            // all reads of this half done
        if (kt + 2 < KT) { load_half(kt + 2); CP_COMMIT(); }
    }

    // -------- epilogue --------
    // acc (mi,ni,r): row = wm0+mi*16+(lane>>2)+(r>>1)*8, col = wn0+ni*8+(lane&3)*2+(r&1)
    if (EPI == 0) {
        #pragma unroll
        for (int mi = 0; mi < 4; mi++)
            #pragma unroll
            for (int ni = 0; ni < 4; ni++) {
                long row = m0 + wm0 + mi * 16 + (lane >> 2);
                int  col = n0 + wn0 + ni * 8 + (lane & 3) * 2;
                float* cp = C + z * sC + row * (long)ldc + col;
                *reinterpret_cast<float2*>(cp) =
                    make_float2(acc[mi][ni][0], acc[mi][ni][1]);
                *reinterpret_cast<float2*>(cp + 8L * ldc) =
                    make_float2(acc[mi][ni][2], acc[mi][ni][3]);
            }
    } else if (EPI == 1) {
        #pragma unroll
        for (int mi = 0; mi < 4; mi++)
            #pragma unroll
            for (int ni = 0; ni < 4; ni++) {
                long row = m0 + wm0 + mi * 16 + (lane >> 2);
                int  col = n0 + wn0 + ni * 8 + (lane & 3) * 2;
                #pragma unroll
                for (int r = 0; r < 4; r += 2) {
                    long rr = row + (r >> 1) * 8;
                    uint32_t hp, lp;
                    split2(acc[mi][ni][r] + bias[col],
                           acc[mi][ni][r + 1] + bias[col + 1], &hp, &lp);
                    *reinterpret_cast<uint32_t*>(Eh + rr * 512 + col) = hp;
                    *reinterpret_cast<uint32_t*>(El + rr * 512 + col) = lp;
                }
            }
    } else {
        // stage 128x128 fp32 tile into smem (pitch 132), then window-sum/pool/relu
        float* buf = reinterpret_cast<float*>(smem);
        #pragma unroll
        for (int mi = 0; mi < 4; mi++)
            #pragma unroll
            for (int ni = 0; ni < 4; ni++) {
                int row = wm0 + mi * 16 + (lane >> 2);
                int col = wn0 + ni * 8 + (lane & 3) * 2;
                *reinterpret_cast<float2*>(buf + row * 132 + col) =
                    make_float2(acc[mi][ni][0], acc[mi][ni][1]);
                *reinterpret_cast<float2*>(buf + (row + 8) * 132 + col) =
                    make_float2(acc[mi][ni][2], acc[mi][ni][3]);
            }
        __syncthreads();
        if (tid < 128) {
            int lab = tid >> 5, f = tid & 31;       // 4 labels x 32 filters
            const float* g = buf + (lab * 32) * 132 + f * 4;
            float P1 = 0.f, P2 = 0.f, P3 = 0.f, best = -FLT_MAX;
            #pragma unroll
            for (int s = 0; s < 32; s++) {
                float4 q = *reinterpret_cast<const float4*>(g + s * 132);
                if (s >= 3) best = fmaxf(best, P3 + q.w);   // completes window t = s-3
                P3 = P2 + q.z;
                P2 = P1 + q.y;
                P1 = q.x;
            }
            int  fg    = (n0 >> 2) + f;                     // global filter
            long lab_g = (m0 >> 5) + lab;                   // global label
            float v = fmaxf(best + bias[fg], 0.f);
            bf16 h, l; split(v, &h, &l);
            Eh[lab_g * 512 + fg] = h;
            El[lab_g * 512 + fg] = l;
        }
    }
}

// ---------------- prep kernels (vectorized: float2 reads, bf16x2 stores) ----------------
__global__ void k_prep_A(const float* __restrict__ reps) {
    long idx = (long)blockIdx.x * 256 + threadIdx.x;     // 131072*160 items
    long row = idx / 160;
    int  pr  = (int)(idx - row * 160);                   // k pair index
    float2 v = make_float2(0.f, 0.f);
    if (pr < 150) v = *reinterpret_cast<const float2*>(reps + row * 300 + 2 * pr);
    uint32_t hp, lp;
    split2(v.x, v.y, &hp, &lp);
    reinterpret_cast<uint32_t*>(g_Ah)[row * 160 + pr] = hp;
    reinterpret_cast<uint32_t*>(g_Al)[row * 160 + pr] = lp;
}
__global__ void k_prep_B(const float* __restrict__ cw) {
    int c = blockIdx.x, p = threadIdx.x;                 // 2048 x 160 (e pairs)
    int f = c >> 2, k = c & 3;
    int e0 = 2 * p;
    float a = (e0     < 300) ? cw[f * 1200 + e0 * 4 + k]       : 0.f;
    float b = (e0 + 1 < 300) ? cw[f * 1200 + (e0 + 1) * 4 + k] : 0.f;
    uint32_t hp, lp;
    split2(a, b, &hp, &lp);
    reinterpret_cast<uint32_t*>(g_Bh)[c * 160 + p] = hp;
    reinterpret_cast<uint32_t*>(g_Bl)[c * 160 + p] = lp;
}
__global__ void k_prep_lin(const float* __restrict__ lw) {
    int i = blockIdx.x * 256 + threadIdx.x;              // 131072 pairs
    float2 v = *reinterpret_cast<const float2*>(lw + 2L * i);
    uint32_t hp, lp;
    split2(v.x, v.y, &hp, &lp);
    reinterpret_cast<uint32_t*>(g_lnh)[i] = hp;
    reinterpret_cast<uint32_t*>(g_lnl)[i] = lp;
}
__global__ void k_prep_x(const float* __restrict__ x) {
    long i = (long)blockIdx.x * 256 + threadIdx.x;       // 2,097,152 pairs
    float2 v = *reinterpret_cast<const float2*>(x + 2L * i);
    uint32_t hp, lp;
    split2(v.x, v.y, &hp, &lp);
    reinterpret_cast<uint32_t*>(g_xh)[i] = hp;
    reinterpret_cast<uint32_t*>(g_xl)[i] = lp;
}

// ---------------- fused softmax + sparse P@x ----------------
// One warp per (b,n) row. Exact softmax denominator over all 512 logits;
// only survivors with p > 1e-7 contribute to out[b,n,:] = sum_l p_l * x[b,l,:].
__global__ void __launch_bounds__(256)
k_softmax_spmm(const float* __restrict__ S, const float* __restrict__ x,
               float* __restrict__ out)
{
    const long row  = (long)blockIdx.x * 8 + (threadIdx.x >> 5);  // 0..65535
    const int  lane = threadIdx.x & 31;
    const float* p  = S + row * 512;
    const float* xb = x + (row >> 12) * 262144;          // x[b]

    float v[16], m = -FLT_MAX;
    #pragma unroll
    for (int i = 0; i < 16; i++) { v[i] = p[lane + 32 * i]; m = fmaxf(m, v[i]); }
    #pragma unroll
    for (int o = 16; o > 0; o >>= 1) m = fmaxf(m, __shfl_xor_sync(0xffffffffu, m, o));

    float s = 0.f;
    #pragma unroll
    for (int i = 0; i < 16; i++) { v[i] = expf(v[i] - m); s += v[i]; }
    #pragma unroll
    for (int o = 16; o > 0; o >>= 1) s += __shfl_xor_sync(0xffffffffu, s, o);

    const float thr = s * 1e-7f;
    float acc[16];
    #pragma unroll
    for (int c = 0; c < 16; c++) acc[c] = 0.f;

    #pragma unroll
    for (int j = 0; j < 16; j++) {
        unsigned mask = __ballot_sync(0xffffffffu, v[j] > thr);
        while (mask) {
            int src = __ffs(mask) - 1;
            mask &= mask - 1;
            float pv = __shfl_sync(0xffffffffu, v[j], src);
            const float* xr = xb + (long)(src + 32 * j) * 512;
            #pragma unroll
            for (int c = 0; c < 16; c++)
                acc[c] = fmaf(pv, xr[lane + 32 * c], acc[c]);
        }
    }
    const float inv = 1.f / s;
    float* op = out + row * 512;
    #pragma unroll
    for (int c = 0; c < 16; c++) op[lane + 32 * c] = acc[c] * inv;
}

// ---------------- launch ----------------
extern "C" void kernel_launch(void* const* d_in, const int* in_sizes, int n_in,
                              void* d_out, int out_size)
{
    const float* x      = (const float*)d_in[0];
    const float* reps   = (const float*)d_in[1];
    const float* conv_w = (const float*)d_in[2];
    const float* conv_b = (const float*)d_in[3];
    const float* lin_w  = (const float*)d_in[4];
    const float* lin_b  = (const float*)d_in[5];
    float* out = (float*)d_out;

    cudaFuncSetAttribute(mmagemm<0>, cudaFuncAttributeMaxDynamicSharedMemorySize, SMEMSZ);
    cudaFuncSetAttribute(mmagemm<1>, cudaFuncAttributeMaxDynamicSharedMemorySize, SMEMSZ);
    cudaFuncSetAttribute(mmagemm<2>, cudaFuncAttributeMaxDynamicSharedMemorySize, SMEMSZ);

    bf16 *Ah, *Al, *Bh, *Bl, *lnh, *lnl, *xh, *xl, *r0h, *r0l, *rh, *rl;
    float* S;
    cudaGetSymbolAddress((void**)&Ah, g_Ah);   cudaGetSymbolAddress((void**)&Al, g_Al);
    cudaGetSymbolAddress((void**)&Bh, g_Bh);   cudaGetSymbolAddress((void**)&Bl, g_Bl);
    cudaGetSymbolAddress((void**)&lnh, g_lnh); cudaGetSymbolAddress((void**)&lnl, g_lnl);
    cudaGetSymbolAddress((void**)&xh, g_xh);   cudaGetSymbolAddress((void**)&xl, g_xl);
    cudaGetSymbolAddress((void**)&r0h, g_r0h); cudaGetSymbolAddress((void**)&r0l, g_r0l);
    cudaGetSymbolAddress((void**)&rh, g_rh);   cudaGetSymbolAddress((void**)&rl, g_rl);
    cudaGetSymbolAddress((void**)&S, g_S);

    // operand prep (vectorized)
    k_prep_A<<<81920, 256>>>(reps);              // 131072*160 / 256
    k_prep_B<<<2048, 160>>>(conv_w);
    k_prep_lin<<<512, 256>>>(lin_w);
    k_prep_x<<<8192, 256>>>(x);                  // 2,097,152 / 256

    // conv GEMM (131072 x 2048, Kc=304, stride 320) + fused window+pool+relu -> r0
    mmagemm<2><<<dim3(16, 1024, 1), 256, SMEMSZ>>>(
        Ah, Al, Bh, Bl, 320, 304, 0, 0, nullptr, 0, 0, conv_b, r0h, r0l);

    // linear (4096 x 512, K=512) + bias -> r (split)
    mmagemm<1><<<dim3(4, 32, 1), 256, SMEMSZ>>>(
        r0h, r0l, lnh, lnl, 512, 512, 0, 0, nullptr, 0, 0, lin_b, rh, rl);

    // logits per batch: S[b] = r @ x[b]^T  (4096 x 512)
    mmagemm<0><<<dim3(4, 32, 16), 256, SMEMSZ>>>(
        rh, rl, xh, xl, 512, 512, 0, 262144, S, 2097152, 512, nullptr, nullptr, nullptr);

    // fused softmax + sparse P@x -> out
    k_softmax_spmm<<<(16 * 4096) / 8, 256>>>(S, x, out);
}

// round 17
// speedup vs baseline: 4.3922x; 1.0014x over previous
#include <cuda_runtime.h>
#include <cuda_bf16.h>
#include <math.h>
#include <cfloat>
#include <cstdint>

typedef __nv_bfloat16 bf16;

// ============================================================================
// x(16,512,512) reps(4096,32,300) conv_w(512,300,4) conv_b(512)
// lin_w(512,512) lin_b(512) -> out(16,4096,512) fp32
// GEMMs via mma.sync.m16n8k16 bf16, 3-term split: hi*hi + hi*lo + lo*hi.
// Final P@x = fused softmax + thresholded sparse weighted sum.
// Conv K = 304 (19 k16 steps), stride 304; KC templated for full unroll.
// ============================================================================

// ---------------- static scratch ----------------
__device__ __align__(16) bf16 g_Ah[131072L * 320];   // conv A hi (stride 304 + slack)
__device__ __align__(16) bf16 g_Al[131072L * 320];   // conv A lo
__device__ __align__(16) bf16 g_Bh[2048 * 320];      // conv B: [c=f*4+k][e], stride 304
__device__ __align__(16) bf16 g_Bl[2048 * 320];
__device__ __align__(16) bf16 g_lnh[512 * 512];      // lin_w [f][c] (native = B layout)
__device__ __align__(16) bf16 g_lnl[512 * 512];
__device__ __align__(16) bf16 g_xh[16L * 512 * 512]; // x elementwise (B of logits)
__device__ __align__(16) bf16 g_xl[16L * 512 * 512];
__device__ __align__(16) bf16 g_r0h[4096 * 512];     // conv+pool+relu out hi/lo
__device__ __align__(16) bf16 g_r0l[4096 * 512];
__device__ __align__(16) bf16 g_rh[4096 * 512];      // after linear hi/lo
__device__ __align__(16) bf16 g_rl[4096 * 512];
__device__ float g_S[16L * 4096 * 512];              // logits fp32

// ---------------- helpers ----------------
__device__ __forceinline__ uint32_t smem_u32(const void* p) {
    uint32_t a;
    asm("{ .reg .u64 t; cvta.to.shared.u64 t, %1; cvt.u32.u64 %0, t; }" : "=r"(a) : "l"(p));
    return a;
}
__device__ __forceinline__ void cpasync16(uint32_t dst, const void* src) {
    asm volatile("cp.async.cg.shared.global [%0], [%1], 16;" :: "r"(dst), "l"(src) : "memory");
}
#define CP_COMMIT() asm volatile("cp.async.commit_group;" ::: "memory")
#define CP_WAIT1()  asm volatile("cp.async.wait_group 1;" ::: "memory")
#define CP_WAIT0()  asm volatile("cp.async.wait_group 0;" ::: "memory")

__device__ __forceinline__ void ldsm4(uint32_t* r, uint32_t addr) {
    asm volatile("ldmatrix.sync.aligned.m8n8.x4.shared.b16 {%0,%1,%2,%3}, [%4];"
                 : "=r"(r[0]), "=r"(r[1]), "=r"(r[2]), "=r"(r[3]) : "r"(addr));
}
__device__ __forceinline__ void mma16816(float* c, const uint32_t* a, const uint32_t* b) {
    asm volatile("mma.sync.aligned.m16n8k16.row.col.f32.bf16.bf16.f32 "
        "{%0,%1,%2,%3}, {%4,%5,%6,%7}, {%8,%9}, {%0,%1,%2,%3};"
        : "+f"(c[0]), "+f"(c[1]), "+f"(c[2]), "+f"(c[3])
        : "r"(a[0]), "r"(a[1]), "r"(a[2]), "r"(a[3]), "r"(b[0]), "r"(b[1]));
}
__device__ __forceinline__ uint32_t swz(uint32_t off) { return off ^ ((off >> 3) & 0x70); }
__device__ __forceinline__ void split(float v, bf16* h, bf16* l) {
    bf16 hh = __float2bfloat16(v);
    *h = hh;
    *l = __float2bfloat16(v - __bfloat162float(hh));
}
// split two floats, return packed bf16x2 words (element 0 in low 16 bits)
__device__ __forceinline__ void split2(float a, float b, uint32_t* hp, uint32_t* lp) {
    bf16 h0, l0, h1, l1;
    split(a, &h0, &l0);
    split(b, &h1, &l1);
    *hp = (uint32_t)__bfloat16_as_ushort(h0) | ((uint32_t)__bfloat16_as_ushort(h1) << 16);
    *lp = (uint32_t)__bfloat16_as_ushort(l0) | ((uint32_t)__bfloat16_as_ushort(l1) << 16);
}
// split a float4 into hi/lo uint2 (4 packed bf16 each)
__device__ __forceinline__ void split4(float4 v, uint2* hp, uint2* lp) {
    split2(v.x, v.y, &hp->x, &lp->x);
    split2(v.z, v.w, &hp->y, &lp->y);
}

// ---------------- GEMM: D(128x128) = A(128xKC) . B(128xKC)^T, 3-term bf16 split -------
// 8 warps as 2(M) x 4(N); warp tile 64x32; K-step 32; 2-half ring inside 128B rows.
// KC = compute K = memory stride (elements, multiple of 16).
// Smem tiles (128 rows x 128B, SW128): Ah@0 Al@16K Bh@32K Bl@48K = 64KB.
// EPI 0: store fp32 C   EPI 1: +bias, split -> Eh/El   EPI 2: conv window+pool+relu
static constexpr int SMEMSZ = 128 * 132 * 4;           // 67584 (EPI2 buf >= 64KB operands)

template <int EPI, int KC>
__global__ void __launch_bounds__(256, 2)
mmagemm(const bf16* __restrict__ Ah, const bf16* __restrict__ Al,
        const bf16* __restrict__ Bh, const bf16* __restrict__ Bl,
        long sA, long sB,
        float* __restrict__ C, long sC, int ldc,
        const float* __restrict__ bias,
        bf16* __restrict__ Eh, bf16* __restrict__ El)
{
    constexpr int K = KC;                   // memory stride
    constexpr int KT = (KC + 31) >> 5;      // k32 steps (last may be half)
    constexpr bool HALF_LAST = ((KC & 31) == 16);

    extern __shared__ char smem[];
    const uint32_t sb = smem_u32(smem);
    const int tid = threadIdx.x, wid = tid >> 5, lane = tid & 31;
    const int wm0 = (wid >> 2) * 64;       // warp row offset in tile
    const int wn0 = (wid & 3) * 32;        // warp col offset in tile
    const long z = blockIdx.z;
    const bf16* pA[2] = { Ah + z * sA, Al + z * sA };
    const bf16* pB[2] = { Bh + z * sB, Bl + z * sB };
    const long m0 = (long)blockIdx.y * 128;
    const int  n0 = blockIdx.x * 128;

    float acc[4][4][4];
    #pragma unroll
    for (int mi = 0; mi < 4; mi++)
        #pragma unroll
        for (int ni = 0; ni < 4; ni++)
            #pragma unroll
            for (int r = 0; r < 4; r++)
                acc[mi][ni][r] = 0.f;

    // load one k32 block (32KB: 4 tiles x 128 rows x 64B) into half (kt2&1) of rows
    auto load_half = [&](int kt2) {
        const int h = (kt2 & 1) * 64;
        const int k0 = kt2 * 32;
        const bf16* srcs[4] = { pA[0] + m0 * K + k0, pA[1] + m0 * K + k0,
                                pB[0] + (long)n0 * K + k0, pB[1] + (long)n0 * K + k0 };
        #pragma unroll
        for (int t = 0; t < 4; t++) {
            uint32_t tb = sb + t * 16384;
            const bf16* sp = srcs[t];
            #pragma unroll
            for (int i = 0; i < 2; i++) {
                int c = tid + i * 256;              // 0..511
                int row = c >> 2, c16 = c & 3;
                cpasync16(tb + swz(row * 128 + h + c16 * 16), sp + (long)row * K + c16 * 8);
            }
        }
    };

    load_half(0); CP_COMMIT();
    load_half(1); CP_COMMIT();

    for (int kt = 0; kt < KT; kt++) {
        if (kt + 1 < KT) { CP_WAIT1(); } else { CP_WAIT0(); }
        __syncthreads();                            // data for kt ready, all warps here
        const uint32_t hoff = (kt & 1) * 64;

        #pragma unroll
        for (int kk = 0; kk < 2; kk++) {
            if (HALF_LAST && kt == KT - 1 && kk == 1) break;   // constexpr-gated
            uint32_t a_h[4][4], a_l[4][4];
            #pragma unroll
            for (int mi = 0; mi < 4; mi++) {
                uint32_t off = (uint32_t)(wm0 + mi * 16 + (lane & 15)) * 128
                             + hoff + kk * 32 + (lane >> 4) * 16;
                ldsm4(a_h[mi], sb + swz(off));                 // Ah
                ldsm4(a_l[mi], sb + 16384 + swz(off));         // Al
            }
            #pragma unroll
            for (int q = 0; q < 2; q++) {
                uint32_t off = (uint32_t)(wn0 + q * 16 + (lane >> 4) * 8 + (lane & 7)) * 128
                             + hoff + kk * 32 + ((lane >> 3) & 1) * 16;
                uint32_t rh[4], rl[4];
                ldsm4(rh, sb + 32768 + swz(off));              // Bh
                ldsm4(rl, sb + 49152 + swz(off));              // Bl
                #pragma unroll
                for (int half = 0; half < 2; half++) {
                    int ni = 2 * q + half;
                    uint32_t bh[2] = { rh[2 * half], rh[2 * half + 1] };
                    uint32_t bl[2] = { rl[2 * half], rl[2 * half + 1] };
                    #pragma unroll
                    for (int mi = 0; mi < 4; mi++) {
                        mma16816(acc[mi][ni], a_h[mi], bh);
                        mma16816(acc[mi][ni], a_h[mi], bl);
                        mma16816(acc[mi][ni], a_l[mi], bh);
                    }
                }
            }
        }
        __syncthreads();                            // all reads of this half done
        if (kt + 2 < KT) { load_half(kt + 2); CP_COMMIT(); }
    }

    // -------- epilogue --------
    // acc (mi,ni,r): row = wm0+mi*16+(lane>>2)+(r>>1)*8, col = wn0+ni*8+(lane&3)*2+(r&1)
    if (EPI == 0) {
        #pragma unroll
        for (int mi = 0; mi < 4; mi++)
            #pragma unroll
            for (int ni = 0; ni < 4; ni++) {
                long row = m0 + wm0 + mi * 16 + (lane >> 2);
                int  col = n0 + wn0 + ni * 8 + (lane & 3) * 2;
                float* cp = C + z * sC + row * (long)ldc + col;
                *reinterpret_cast<float2*>(cp) =
                    make_float2(acc[mi][ni][0], acc[mi][ni][1]);
                *reinterpret_cast<float2*>(cp + 8L * ldc) =
                    make_float2(acc[mi][ni][2], acc[mi][ni][3]);
            }
    } else if (EPI == 1) {
        #pragma unroll
        for (int mi = 0; mi < 4; mi++)
            #pragma unroll
            for (int ni = 0; ni < 4; ni++) {
                long row = m0 + wm0 + mi * 16 + (lane >> 2);
                int  col = n0 + wn0 + ni * 8 + (lane & 3) * 2;
                #pragma unroll
                for (int r = 0; r < 4; r += 2) {
                    long rr = row + (r >> 1) * 8;
                    uint32_t hp, lp;
                    split2(acc[mi][ni][r] + bias[col],
                           acc[mi][ni][r + 1] + bias[col + 1], &hp, &lp);
                    *reinterpret_cast<uint32_t*>(Eh + rr * 512 + col) = hp;
                    *reinterpret_cast<uint32_t*>(El + rr * 512 + col) = lp;
                }
            }
    } else {
        // stage 128x128 fp32 tile into smem (pitch 132), then window-sum/pool/relu
        float* buf = reinterpret_cast<float*>(smem);
        #pragma unroll
        for (int mi = 0; mi < 4; mi++)
            #pragma unroll
            for (int ni = 0; ni < 4; ni++) {
                int row = wm0 + mi * 16 + (lane >> 2);
                int col = wn0 + ni * 8 + (lane & 3) * 2;
                *reinterpret_cast<float2*>(buf + row * 132 + col) =
                    make_float2(acc[mi][ni][0], acc[mi][ni][1]);
                *reinterpret_cast<float2*>(buf + (row + 8) * 132 + col) =
                    make_float2(acc[mi][ni][2], acc[mi][ni][3]);
            }
        __syncthreads();
        if (tid < 128) {
            int lab = tid >> 5, f = tid & 31;       // 4 labels x 32 filters
            const float* g = buf + (lab * 32) * 132 + f * 4;
            float P1 = 0.f, P2 = 0.f, P3 = 0.f, best = -FLT_MAX;
            #pragma unroll
            for (int s = 0; s < 32; s++) {
                float4 q = *reinterpret_cast<const float4*>(g + s * 132);
                if (s >= 3) best = fmaxf(best, P3 + q.w);   // completes window t = s-3
                P3 = P2 + q.z;
                P2 = P1 + q.y;
                P1 = q.x;
            }
            int  fg    = (n0 >> 2) + f;                     // global filter
            long lab_g = (m0 >> 5) + lab;                   // global label
            float v = fmaxf(best + bias[fg], 0.f);
            bf16 h, l; split(v, &h, &l);
            Eh[lab_g * 512 + fg] = h;
            El[lab_g * 512 + fg] = l;
        }
    }
}

// ---------------- prep kernels (float4 reads, uint4 packed-bf16 stores) ----------------
// A: 38 threads per row, 8 elements each (2 float4 loads); row stride 1200B is 16B-aligned.
// Writes 152 bf16x2 pairs per row (stride 304); elements 300..303 zeroed.
__global__ void k_prep_A(const float* __restrict__ reps) {
    int r_in_b = threadIdx.x / 38;
    int t = threadIdx.x - r_in_b * 38;                   // 0..37
    long row = (long)blockIdx.x * 6 + r_in_b;
    if (row >= 131072) return;
    const float* rp = reps + row * 300;
    int e0 = t * 8;                                      // 0..296
    float4 a = *reinterpret_cast<const float4*>(rp + e0);
    float4 b = make_float4(0.f, 0.f, 0.f, 0.f);
    if (t < 37) b = *reinterpret_cast<const float4*>(rp + e0 + 4);
    uint2 h0, l0, h1, l1;
    split4(a, &h0, &l0);
    split4(b, &h1, &l1);
    long o = row * 152 + 4 * t;                          // uint32 index
    *reinterpret_cast<uint4*>(reinterpret_cast<uint32_t*>(g_Ah) + o) =
        make_uint4(h0.x, h0.y, h1.x, h1.y);
    *reinterpret_cast<uint4*>(reinterpret_cast<uint32_t*>(g_Al) + o) =
        make_uint4(l0.x, l0.y, l1.x, l1.y);
}
__global__ void k_prep_B(const float* __restrict__ cw) {
    int c = blockIdx.x, p = threadIdx.x;                 // 2048 x 152 (e pairs)
    int f = c >> 2, k = c & 3;
    int e0 = 2 * p;
    float a = (e0     < 300) ? cw[f * 1200 + e0 * 4 + k]       : 0.f;
    float b = (e0 + 1 < 300) ? cw[f * 1200 + (e0 + 1) * 4 + k] : 0.f;
    uint32_t hp, lp;
    split2(a, b, &hp, &lp);
    reinterpret_cast<uint32_t*>(g_Bh)[c * 152 + p] = hp;
    reinterpret_cast<uint32_t*>(g_Bl)[c * 152 + p] = lp;
}
__global__ void k_prep_lin(const float* __restrict__ lw) {
    long i = (long)blockIdx.x * 256 + threadIdx.x;       // 32768 threads x 8 floats
    float4 a = *reinterpret_cast<const float4*>(lw + 8 * i);
    float4 b = *reinterpret_cast<const float4*>(lw + 8 * i + 4);
    uint2 h0, l0, h1, l1;
    split4(a, &h0, &l0);
    split4(b, &h1, &l1);
    *reinterpret_cast<uint4*>(reinterpret_cast<uint32_t*>(g_lnh) + 4 * i) =
        make_uint4(h0.x, h0.y, h1.x, h1.y);
    *reinterpret_cast<uint4*>(reinterpret_cast<uint32_t*>(g_lnl) + 4 * i) =
        make_uint4(l0.x, l0.y, l1.x, l1.y);
}
__global__ void k_prep_x(const float* __restrict__ x) {
    long i = (long)blockIdx.x * 256 + threadIdx.x;       // 524288 threads x 8 floats
    float4 a = *reinterpret_cast<const float4*>(x + 8 * i);
    float4 b = *reinterpret_cast<const float4*>(x + 8 * i + 4);
    uint2 h0, l0, h1, l1;
    split4(a, &h0, &l0);
    split4(b, &h1, &l1);
    *reinterpret_cast<uint4*>(reinterpret_cast<uint32_t*>(g_xh) + 4 * i) =
        make_uint4(h0.x, h0.y, h1.x, h1.y);
    *reinterpret_cast<uint4*>(reinterpret_cast<uint32_t*>(g_xl) + 4 * i) =
        make_uint4(l0.x, l0.y, l1.x, l1.y);
}

// ---------------- fused softmax + sparse P@x ----------------
// One warp per (b,n) row. Exact softmax denominator over all 512 logits;
// only survivors with p > 1e-7 contribute to out[b,n,:] = sum_l p_l * x[b,l,:].
__global__ void __launch_bounds__(256)
k_softmax_spmm(const float* __restrict__ S, const float* __restrict__ x,
               float* __restrict__ out)
{
    const long row  = (long)blockIdx.x * 8 + (threadIdx.x >> 5);  // 0..65535
    const int  lane = threadIdx.x & 31;
    const float* p  = S + row * 512;
    const float* xb = x + (row >> 12) * 262144;          // x[b]

    float v[16], m = -FLT_MAX;
    #pragma unroll
    for (int i = 0; i < 16; i++) { v[i] = p[lane + 32 * i]; m = fmaxf(m, v[i]); }
    #pragma unroll
    for (int o = 16; o > 0; o >>= 1) m = fmaxf(m, __shfl_xor_sync(0xffffffffu, m, o));

    float s = 0.f;
    #pragma unroll
    for (int i = 0; i < 16; i++) { v[i] = expf(v[i] - m); s += v[i]; }
    #pragma unroll
    for (int o = 16; o > 0; o >>= 1) s += __shfl_xor_sync(0xffffffffu, s, o);

    const float thr = s * 1e-7f;
    float acc[16];
    #pragma unroll
    for (int c = 0; c < 16; c++) acc[c] = 0.f;

    #pragma unroll
    for (int j = 0; j < 16; j++) {
        unsigned mask = __ballot_sync(0xffffffffu, v[j] > thr);
        while (mask) {
            int src = __ffs(mask) - 1;
            mask &= mask - 1;
            float pv = __shfl_sync(0xffffffffu, v[j], src);
            const float* xr = xb + (long)(src + 32 * j) * 512;
            #pragma unroll
            for (int c = 0; c < 16; c++)
                acc[c] = fmaf(pv, xr[lane + 32 * c], acc[c]);
        }
    }
    const float inv = 1.f / s;
    float* op = out + row * 512;
    #pragma unroll
    for (int c = 0; c < 16; c++) op[lane + 32 * c] = acc[c] * inv;
}

// ---------------- launch ----------------
extern "C" void kernel_launch(void* const* d_in, const int* in_sizes, int n_in,
                              void* d_out, int out_size)
{
    const float* x      = (const float*)d_in[0];
    const float* reps   = (const float*)d_in[1];
    const float* conv_w = (const float*)d_in[2];
    const float* conv_b = (const float*)d_in[3];
    const float* lin_w  = (const float*)d_in[4];
    const float* lin_b  = (const float*)d_in[5];
    float* out = (float*)d_out;

    cudaFuncSetAttribute(mmagemm<0, 512>, cudaFuncAttributeMaxDynamicSharedMemorySize, SMEMSZ);
    cudaFuncSetAttribute(mmagemm<1, 512>, cudaFuncAttributeMaxDynamicSharedMemorySize, SMEMSZ);
    cudaFuncSetAttribute(mmagemm<2, 304>, cudaFuncAttributeMaxDynamicSharedMemorySize, SMEMSZ);

    bf16 *Ah, *Al, *Bh, *Bl, *lnh, *lnl, *xh, *xl, *r0h, *r0l, *rh, *rl;
    float* S;
    cudaGetSymbolAddress((void**)&Ah, g_Ah);   cudaGetSymbolAddress((void**)&Al, g_Al);
    cudaGetSymbolAddress((void**)&Bh, g_Bh);   cudaGetSymbolAddress((void**)&Bl, g_Bl);
    cudaGetSymbolAddress((void**)&lnh, g_lnh); cudaGetSymbolAddress((void**)&lnl, g_lnl);
    cudaGetSymbolAddress((void**)&xh, g_xh);   cudaGetSymbolAddress((void**)&xl, g_xl);
    cudaGetSymbolAddress((void**)&r0h, g_r0h); cudaGetSymbolAddress((void**)&r0l, g_r0l);
    cudaGetSymbolAddress((void**)&rh, g_rh);   cudaGetSymbolAddress((void**)&rl, g_rl);
    cudaGetSymbolAddress((void**)&S, g_S);

    // operand prep (vectorized)
    k_prep_A<<<(131072 + 5) / 6, 228>>>(reps);   // 6 rows x 38 threads per block
    k_prep_B<<<2048, 152>>>(conv_w);
    k_prep_lin<<<128, 256>>>(lin_w);             // 262144 floats / 8 / 256
    k_prep_x<<<2048, 256>>>(x);                  // 4194304 floats / 8 / 256

    // conv GEMM (131072 x 2048, KC=304) + fused window+pool+relu -> r0
    mmagemm<2, 304><<<dim3(16, 1024, 1), 256, SMEMSZ>>>(
        Ah, Al, Bh, Bl, 0, 0, nullptr, 0, 0, conv_b, r0h, r0l);

    // linear (4096 x 512, K=512) + bias -> r (split)
    mmagemm<1, 512><<<dim3(4, 32, 1), 256, SMEMSZ>>>(
        r0h, r0l, lnh, lnl, 0, 0, nullptr, 0, 0, lin_b, rh, rl);

    // logits per batch: S[b] = r @ x[b]^T  (4096 x 512)
    mmagemm<0, 512><<<dim3(4, 32, 16), 256, SMEMSZ>>>(
        rh, rl, xh, xl, 0, 262144, S, 2097152, 512, nullptr, nullptr, nullptr);

    // fused softmax + sparse P@x -> out
    k_softmax_spmm<<<(16 * 4096) / 8, 256>>>(S, x, out);
}